// round 4
// baseline (speedup 1.0000x reference)
#include <cuda_runtime.h>
#include <cuda_bf16.h>

// Problem constants (fixed by the reference)
constexpr long long Nn   = 50000;
constexpr long long Ee   = 800000;
constexpr long long Hdim = 256;   // H1 == H2
constexpr long long Odim = 128;   // OUT == IN

// Scratch layout inside one __device__ array (no allocations allowed).
// Index scratch is int32 but stored in float-sized slots (4B each).
constexpr long long OFF_DINV1 = 0;
constexpr long long OFF_DINV2 = OFF_DINV1 + Nn;
constexpr long long OFF_IDX1  = OFF_DINV2 + Nn;            // src1,dst1  [2E] int32
constexpr long long OFF_IDX2  = OFF_IDX1  + 2 * Ee;        // src2,dst2  [2E] int32
constexpr long long OFF_H0    = OFF_IDX2  + 2 * Ee;        // x @ W0   [N,256]
constexpr long long OFF_HB    = OFF_H0    + Nn * Hdim;     // x @ W1   [N,256]
constexpr long long OFF_A1    = OFF_HB    + Nn * Hdim;     // agg1     [N,256]
constexpr long long OFF_A2    = OFF_A1    + Nn * Hdim;     // agg2     [N,256]
constexpr long long OFF_G1    = OFF_A2    + Nn * Hdim;     // tmp1@W2  [N,128]
constexpr long long OFF_G2    = OFF_G1    + Nn * Odim;     // tmp2@W3  [N,128]
constexpr long long SCRATCH   = OFF_G2    + Nn * Odim;

__device__ float g_scratch[SCRATCH];
__device__ int   g_is64;   // 1 if edge indices are int64, 0 if int32

// ---------------------------------------------------------------------------
// index dtype detection + decode
// ---------------------------------------------------------------------------
__global__ void k_flag_init() { g_is64 = 1; }

// Interpret the first `words` 8-byte words of p as int64 indices. If the data
// is really int64, these are the src row, all in [0, n). If it's int32, the
// words are (lo + hi*2^32) with hi ~ U[0, n) -> essentially always out of
// range, so any violation marks the data as int32.
__global__ void k_detect(const long long* __restrict__ p, int words, int n) {
    int i = blockIdx.x * blockDim.x + threadIdx.x;
    if (i < words) {
        long long v = p[i];
        if (v < 0 || v >= n) g_is64 = 0;   // benign race: all writers write 0
    }
}

// Decode `count` indices from raw buffer into int32 scratch.
__global__ void k_convert(const void* __restrict__ p, int* __restrict__ out, int count) {
    int i = blockIdx.x * blockDim.x + threadIdx.x;
    if (i < count) {
        int v;
        if (g_is64) v = (int)((const long long*)p)[i];
        else        v = ((const int*)p)[i];
        out[i] = v;
    }
}

// ---------------------------------------------------------------------------
// small elementwise kernels
// ---------------------------------------------------------------------------
__global__ void k_zero(float* __restrict__ p, int n) {
    int i = blockIdx.x * blockDim.x + threadIdx.x;
    if (i < n) p[i] = 0.0f;
}

__global__ void k_deg(const int* __restrict__ dst1,
                      const int* __restrict__ dst2,
                      float* __restrict__ deg1, float* __restrict__ deg2, int E) {
    int e = blockIdx.x * blockDim.x + threadIdx.x;
    if (e < E) {
        atomicAdd(&deg1[dst1[e]], 1.0f);
        atomicAdd(&deg2[dst2[e]], 1.0f);
    }
}

__global__ void k_dinv(float* __restrict__ d1, float* __restrict__ d2, int n) {
    int i = blockIdx.x * blockDim.x + threadIdx.x;
    if (i < n) {
        d1[i] = rsqrtf(d1[i] + 1.0f);
        d2[i] = rsqrtf(d2[i] + 1.0f);
    }
}

// A[i] = H[i] * dinv[node]^2   (self-loop term initializes the agg buffer)
__global__ void k_selfinit(const float* __restrict__ H, const float* __restrict__ dinv,
                           float* __restrict__ A, int total, int C) {
    int i = blockIdx.x * blockDim.x + threadIdx.x;
    if (i < total) {
        float dv = dinv[i / C];
        A[i] = H[i] * dv * dv;
    }
}

// out = G1*dinv1^2 + G2*dinv2^2 + b2 + b3  (then the two scatters add on top)
__global__ void k_outinit(const float* __restrict__ G1, const float* __restrict__ G2,
                          const float* __restrict__ dinv1, const float* __restrict__ dinv2,
                          const float* __restrict__ b2, const float* __restrict__ b3,
                          float* __restrict__ out, int total, int C) {
    int i = blockIdx.x * blockDim.x + threadIdx.x;
    if (i < total) {
        int node = i / C;
        int c    = i - node * C;
        float a = dinv1[node], b = dinv2[node];
        out[i] = G1[i] * a * a + G2[i] * b * b + b2[c] + b3[c];
    }
}

// ---------------------------------------------------------------------------
// fp32 tiled GEMM: C[M,Ncol] = op(A[M,K]) * B[K,Ncol]
// op = identity, or relu(A + biasA[k]) when PRELU (fuses layer-1 bias+ReLU)
// 64x64 tile, BK=16, 256 threads, 4x4 per thread
// ---------------------------------------------------------------------------
template <bool PRELU>
__global__ __launch_bounds__(256) void k_gemm(const float* __restrict__ A,
                                              const float* __restrict__ biasA,
                                              const float* __restrict__ B,
                                              float* __restrict__ C,
                                              int M, int K, int Ncol) {
    __shared__ float As[16][65];  // [k][row], padded to kill store conflicts
    __shared__ float Bs[16][64];  // [k][col]

    const int rowBase = blockIdx.y * 64;
    const int colBase = blockIdx.x * 64;
    const int tid = threadIdx.x;
    const int ty = tid >> 4;   // 0..15
    const int tx = tid & 15;   // 0..15

    float acc[4][4] = {};

    for (int k0 = 0; k0 < K; k0 += 16) {
        // load A tile (64 rows x 16 k), transposed into As[k][row]
#pragma unroll
        for (int i = 0; i < 4; i++) {
            int idx = tid + i * 256;        // 0..1023
            int r   = idx >> 4;             // row within tile
            int kk  = idx & 15;
            int row = rowBase + r;
            float v = 0.0f;
            if (row < M) {
                v = A[(long long)row * K + k0 + kk];
                if (PRELU) v = fmaxf(v + biasA[k0 + kk], 0.0f);
            }
            As[kk][r] = v;
        }
        // load B tile (16 k x 64 cols)
#pragma unroll
        for (int i = 0; i < 4; i++) {
            int idx = tid + i * 256;
            int kk  = idx >> 6;
            int c   = idx & 63;
            Bs[kk][c] = B[(long long)(k0 + kk) * Ncol + colBase + c];
        }
        __syncthreads();

#pragma unroll
        for (int kk = 0; kk < 16; kk++) {
            float a[4], b[4];
#pragma unroll
            for (int i = 0; i < 4; i++) a[i] = As[kk][ty * 4 + i];
#pragma unroll
            for (int j = 0; j < 4; j++) b[j] = Bs[kk][tx * 4 + j];
#pragma unroll
            for (int i = 0; i < 4; i++)
#pragma unroll
                for (int j = 0; j < 4; j++) acc[i][j] += a[i] * b[j];
        }
        __syncthreads();
    }

#pragma unroll
    for (int i = 0; i < 4; i++) {
        int row = rowBase + ty * 4 + i;
        if (row < M) {
#pragma unroll
            for (int j = 0; j < 4; j++)
                C[(long long)row * Ncol + colBase + tx * 4 + j] = acc[i][j];
        }
    }
}

// ---------------------------------------------------------------------------
// edge scatter: Agg[dst] += H[src] * (dinv[src]*dinv[dst]) using float4 atomics
// one thread per (edge, float4-chunk)
// ---------------------------------------------------------------------------
template <int CHUNKS>  // columns / 4
__global__ __launch_bounds__(256) void k_scatter(const int* __restrict__ src,
                                                 const int* __restrict__ dst,
                                                 const float* __restrict__ dinv,
                                                 const float4* __restrict__ H,
                                                 float4* __restrict__ Agg, int E) {
    long long gid = (long long)blockIdx.x * blockDim.x + threadIdx.x;
    int e = (int)(gid / CHUNKS);
    if (e >= E) return;
    int c = (int)(gid - (long long)e * CHUNKS);
    int s = src[e];
    int d = dst[e];
    float w = dinv[s] * dinv[d];
    float4 h = H[(long long)s * CHUNKS + c];
    float4 v = make_float4(h.x * w, h.y * w, h.z * w, h.w * w);
    atomicAdd(&Agg[(long long)d * CHUNKS + c], v);  // red.global.v4.f32 on sm_90+
}

// ---------------------------------------------------------------------------
extern "C" void kernel_launch(void* const* d_in, const int* in_sizes, int n_in,
                              void* d_out, int out_size) {
    const float* x   = (const float*)d_in[0];
    const void*  ei  = d_in[1];
    const void*  ei2 = d_in[2];
    const float* W0 = (const float*)d_in[3];
    const float* b0 = (const float*)d_in[4];
    const float* W1 = (const float*)d_in[5];
    const float* b1 = (const float*)d_in[6];
    const float* W2 = (const float*)d_in[7];
    const float* b2 = (const float*)d_in[8];
    const float* W3 = (const float*)d_in[9];
    const float* b3 = (const float*)d_in[10];

    const int N = in_sizes[0] / 128;   // 50000
    const int E = in_sizes[1] / 2;     // 800000

    float* S = nullptr;
    cudaGetSymbolAddress((void**)&S, g_scratch);
    float* dinv1 = S + OFF_DINV1;
    float* dinv2 = S + OFF_DINV2;
    int*   idx1  = (int*)(S + OFF_IDX1);
    int*   idx2  = (int*)(S + OFF_IDX2);
    float* H0    = S + OFF_H0;
    float* HB    = S + OFF_HB;
    float* A1    = S + OFF_A1;
    float* A2    = S + OFF_A2;
    float* G1    = S + OFF_G1;
    float* G2    = S + OFF_G2;

    float* out = (float*)d_out;

    // 0) detect index dtype (int32 vs int64) and decode to int32 scratch
    k_flag_init<<<1, 1>>>();
    k_detect<<<(E + 255) / 256, 256>>>((const long long*)ei, E, N);
    k_convert<<<(2 * E + 255) / 256, 256>>>(ei,  idx1, 2 * E);
    k_convert<<<(2 * E + 255) / 256, 256>>>(ei2, idx2, 2 * E);

    const int* src1 = idx1;
    const int* dst1 = idx1 + E;
    const int* src2 = idx2;
    const int* dst2 = idx2 + E;

    // 1) degrees -> dinv  (dinv1/dinv2 are contiguous: zero both at once)
    k_zero<<<(2 * N + 255) / 256, 256>>>(dinv1, 2 * N);
    k_deg<<<(E + 255) / 256, 256>>>(dst1, dst2, dinv1, dinv2, E);
    k_dinv<<<(N + 255) / 256, 256>>>(dinv1, dinv2, N);

    // 2) layer-1 GEMMs: H0 = x@W0, HB = x@W1   (M=N, K=128, Ncol=256)
    dim3 g1(256 / 64, (N + 63) / 64);
    k_gemm<false><<<g1, 256>>>(x, nullptr, W0, H0, N, 128, 256);
    k_gemm<false><<<g1, 256>>>(x, nullptr, W1, HB, N, 128, 256);

    // 3) init agg with self-loop term, then scatter edges (float4 atomics)
    k_selfinit<<<(N * 256 + 255) / 256, 256>>>(H0, dinv1, A1, N * 256, 256);
    k_selfinit<<<(N * 256 + 255) / 256, 256>>>(HB, dinv2, A2, N * 256, 256);
    {
        long long work = (long long)E * 64;  // 256 cols / 4
        int blocks = (int)((work + 255) / 256);
        k_scatter<64><<<blocks, 256>>>(src1, dst1, dinv1, (const float4*)H0, (float4*)A1, E);
        k_scatter<64><<<blocks, 256>>>(src2, dst2, dinv2, (const float4*)HB, (float4*)A2, E);
    }

    // 4) layer-2 GEMMs with fused bias+ReLU prologue:
    //    G1 = relu(A1+b0)@W2, G2 = relu(A2+b1)@W3   (K=256, Ncol=128)
    dim3 g2(128 / 64, (N + 63) / 64);
    k_gemm<true><<<g2, 256>>>(A1, b0, W2, G1, N, 256, 128);
    k_gemm<true><<<g2, 256>>>(A2, b1, W3, G2, N, 256, 128);

    // 5) out = G1*dinv1^2 + G2*dinv2^2 + b2 + b3, then scatter both graphs into out
    k_outinit<<<(N * 128 + 255) / 256, 256>>>(G1, G2, dinv1, dinv2, b2, b3, out, N * 128, 128);
    {
        long long work = (long long)E * 32;  // 128 cols / 4
        int blocks = (int)((work + 255) / 256);
        k_scatter<32><<<blocks, 256>>>(src1, dst1, dinv1, (const float4*)G1, (float4*)out, E);
        k_scatter<32><<<blocks, 256>>>(src2, dst2, dinv2, (const float4*)G2, (float4*)out, E);
    }
}

// round 5
// speedup vs baseline: 1.7618x; 1.7618x over previous
#include <cuda_runtime.h>

// Problem constants (fixed by the reference)
constexpr long long Nn = 50000;
constexpr long long Ee = 800000;
constexpr long long RP = 50008;   // rowptr stride (>= Nn+1, multiple of 4)

// Scratch layout inside one __device__ array (no allocations allowed).
// All offsets are multiples of 4 elements -> 16B aligned for float4 views.
constexpr long long OFF_DINV1 = 0;
constexpr long long OFF_DINV2 = OFF_DINV1 + Nn;
constexpr long long OFF_CNT1  = OFF_DINV2 + Nn;            // int
constexpr long long OFF_CNT2  = OFF_CNT1  + Nn;            // int
constexpr long long OFF_RP1   = OFF_CNT2  + Nn;            // int rowptr
constexpr long long OFF_RP2   = OFF_RP1   + RP;
constexpr long long OFF_FP1   = OFF_RP2   + RP;            // int fill cursor
constexpr long long OFF_FP2   = OFF_FP1   + Nn;
constexpr long long OFF_IDX1  = OFF_FP2   + Nn;            // src1,dst1 [2E] int
constexpr long long OFF_IDX2  = OFF_IDX1  + 2 * Ee;        // src2,dst2 [2E] int
constexpr long long OFF_ADJ1  = OFF_IDX2  + 2 * Ee;        // CSR adj   [E] int
constexpr long long OFF_ADJ2  = OFF_ADJ1  + Ee;
constexpr long long OFF_HS1   = OFF_ADJ2  + Ee;            // h0*dinv   [N,256]
constexpr long long OFF_HS2   = OFF_HS1   + Nn * 256;      // h1*dinv   [N,256]
constexpr long long OFF_A1    = OFF_HS2   + Nn * 256;      // agg1      [N,256]
constexpr long long OFF_A2    = OFF_A1    + Nn * 256;      // agg2      [N,256]
constexpr long long OFF_GS1   = OFF_A2    + Nn * 256;      // g1*dinv   [N,128]
constexpr long long OFF_GS2   = OFF_GS1   + Nn * 128;      // g2*dinv   [N,128]
constexpr long long SCRATCH   = OFF_GS2   + Nn * 128;

__device__ float g_scratch[SCRATCH];
__device__ int   g_is64;   // 1 if edge indices are int64, 0 if int32

// ---------------------------------------------------------------------------
// index dtype detection + decode (handles JAX silently downcasting int64->int32)
// ---------------------------------------------------------------------------
__global__ void k_flag_init() { g_is64 = 1; }

__global__ void k_detect(const long long* __restrict__ p, int words, int n) {
    int i = blockIdx.x * blockDim.x + threadIdx.x;
    if (i < words) {
        long long v = p[i];
        if (v < 0 || v >= n) g_is64 = 0;   // benign race: all writers write 0
    }
}

// decode both graphs' index buffers into int32 scratch in one pass
__global__ void k_convert2(const void* __restrict__ p1, const void* __restrict__ p2,
                           int* __restrict__ o1, int* __restrict__ o2, int count) {
    int i = blockIdx.x * blockDim.x + threadIdx.x;
    if (i < count) {
        if (g_is64) {
            o1[i] = (int)((const long long*)p1)[i];
            o2[i] = (int)((const long long*)p2)[i];
        } else {
            o1[i] = ((const int*)p1)[i];
            o2[i] = ((const int*)p2)[i];
        }
    }
}

// ---------------------------------------------------------------------------
// degree / dinv / CSR build
// ---------------------------------------------------------------------------
__global__ void k_zero_int(int* __restrict__ p, int n) {
    int i = blockIdx.x * blockDim.x + threadIdx.x;
    if (i < n) p[i] = 0;
}

__global__ void k_degi(const int* __restrict__ dst1, const int* __restrict__ dst2,
                       int* __restrict__ cnt1, int* __restrict__ cnt2, int E) {
    int e = blockIdx.x * blockDim.x + threadIdx.x;
    if (e < E) {
        atomicAdd(&cnt1[dst1[e]], 1);
        atomicAdd(&cnt2[dst2[e]], 1);
    }
}

// dinv[i] = rsqrt(deg+1); cnt1/cnt2 and dinv1/dinv2 are each contiguous
__global__ void k_dinv(const int* __restrict__ cnt, float* __restrict__ dinv, int n2) {
    int i = blockIdx.x * blockDim.x + threadIdx.x;
    if (i < n2) dinv[i] = rsqrtf((float)cnt[i] + 1.0f);
}

// single-block exclusive scan (warp-shuffle based) for both graphs
__device__ void scan_one(const int* __restrict__ cnt, int* __restrict__ rp,
                         int* __restrict__ fp, int n) {
    __shared__ int wsum[32];
    __shared__ int s_base;
    const int t = threadIdx.x;
    const int lane = t & 31, wid = t >> 5;
    if (t == 0) s_base = 0;
    __syncthreads();
    for (int chunk = 0; chunk < n; chunk += 1024) {
        int v = (chunk + t < n) ? cnt[chunk + t] : 0;
        // warp inclusive scan
        int incl = v;
#pragma unroll
        for (int off = 1; off < 32; off <<= 1) {
            int x = __shfl_up_sync(0xffffffffu, incl, off);
            if (lane >= off) incl += x;
        }
        if (lane == 31) wsum[wid] = incl;
        __syncthreads();
        if (wid == 0) {
            int s = wsum[lane];
#pragma unroll
            for (int off = 1; off < 32; off <<= 1) {
                int x = __shfl_up_sync(0xffffffffu, s, off);
                if (lane >= off) s += x;
            }
            wsum[lane] = s;   // inclusive warp-sum scan
        }
        __syncthreads();
        int warpoff = (wid == 0) ? 0 : wsum[wid - 1];
        int base = s_base;
        __syncthreads();
        if (chunk + t < n) {
            int ex = base + warpoff + incl - v;
            rp[chunk + t] = ex;
            fp[chunk + t] = ex;
        }
        if (t == 0) s_base = base + wsum[31];
        __syncthreads();
    }
    if (t == 0) rp[n] = s_base;
    __syncthreads();
}

__global__ void k_scan(const int* __restrict__ cnt1, const int* __restrict__ cnt2,
                       int* __restrict__ rp1, int* __restrict__ rp2,
                       int* __restrict__ fp1, int* __restrict__ fp2, int n) {
    scan_one(cnt1, rp1, fp1, n);
    scan_one(cnt2, rp2, fp2, n);
}

__global__ void k_fill2(const int* __restrict__ src1, const int* __restrict__ dst1,
                        const int* __restrict__ src2, const int* __restrict__ dst2,
                        int* __restrict__ fp1, int* __restrict__ fp2,
                        int* __restrict__ adj1, int* __restrict__ adj2, int E) {
    int e = blockIdx.x * blockDim.x + threadIdx.x;
    if (e < E) {
        int p1 = atomicAdd(&fp1[dst1[e]], 1);
        adj1[p1] = src1[e];
        int p2 = atomicAdd(&fp2[dst2[e]], 1);
        adj2[p2] = src2[e];
    }
}

// ---------------------------------------------------------------------------
// fp32 GEMM v2: C = op(A[M,K]) * B[K,Ncol] with fused GCN epilogues
//   BM=128, BN=64, BK=16, 256 threads, 8x4 per thread, float4 everywhere.
// MODE 0 (layer1): op=identity.  epi: OutS = h*dv ; OutB = h*dv^2      (A init)
// MODE 1 (layer2a): op=relu(A+biasA). epi: OutS = g*dv ; OutB  = g*dv^2 + b2+b3
// MODE 2 (layer2b): op=relu(A+biasA). epi: OutS = g*dv ; OutB += g*dv^2
// ---------------------------------------------------------------------------
template <int MODE>
__global__ __launch_bounds__(256) void k_gemm2(const float* __restrict__ A,
                                               const float* __restrict__ biasA,
                                               const float* __restrict__ B,
                                               const float* __restrict__ dinv,
                                               float* __restrict__ OutS,
                                               float* __restrict__ OutB,
                                               const float* __restrict__ bias2,
                                               const float* __restrict__ bias3,
                                               int M, int K, int Ncol) {
    __shared__ float As[16][132];   // [k][m], padded
    __shared__ float Bs[16][64];    // [k][n]

    const int rowBase = blockIdx.y * 128;
    const int colBase = blockIdx.x * 64;
    const int tid = threadIdx.x;
    const int ty = tid >> 4;    // 0..15 -> 8 rows each
    const int tx = tid & 15;    // 0..15 -> 4 cols each

    float acc[8][4] = {};

    for (int k0 = 0; k0 < K; k0 += 16) {
        // A tile: 128 rows x 16 k = 512 float4; 2 per thread
#pragma unroll
        for (int t = 0; t < 2; t++) {
            int idx = tid + t * 256;      // 0..511
            int r = idx >> 2;             // row in tile
            int q = idx & 3;              // k quad
            int row = rowBase + r;
            float4 v = make_float4(0.f, 0.f, 0.f, 0.f);
            if (row < M) {
                v = *(const float4*)(A + (long long)row * K + k0 + q * 4);
                if (MODE != 0) {
                    float4 bb = *(const float4*)(biasA + k0 + q * 4);
                    v.x = fmaxf(v.x + bb.x, 0.f);
                    v.y = fmaxf(v.y + bb.y, 0.f);
                    v.z = fmaxf(v.z + bb.z, 0.f);
                    v.w = fmaxf(v.w + bb.w, 0.f);
                }
            }
            As[q * 4 + 0][r] = v.x;
            As[q * 4 + 1][r] = v.y;
            As[q * 4 + 2][r] = v.z;
            As[q * 4 + 3][r] = v.w;
        }
        // B tile: 16 k x 64 n = 256 float4; 1 per thread
        {
            int kk = tid >> 4;
            int c  = (tid & 15) * 4;
            float4 v = *(const float4*)(B + (long long)(k0 + kk) * Ncol + colBase + c);
            *(float4*)&Bs[kk][c] = v;
        }
        __syncthreads();

#pragma unroll
        for (int kk = 0; kk < 16; kk++) {
            float a[8], b[4];
            *(float4*)&a[0] = *(const float4*)&As[kk][ty * 8];
            *(float4*)&a[4] = *(const float4*)&As[kk][ty * 8 + 4];
            *(float4*)&b[0] = *(const float4*)&Bs[kk][tx * 4];
#pragma unroll
            for (int i = 0; i < 8; i++)
#pragma unroll
                for (int j = 0; j < 4; j++) acc[i][j] += a[i] * b[j];
        }
        __syncthreads();
    }

    // epilogue
#pragma unroll
    for (int i = 0; i < 8; i++) {
        int row = rowBase + ty * 8 + i;
        if (row >= M) continue;
        float dv = dinv[row];
        float dv2 = dv * dv;
        long long base = (long long)row * Ncol + colBase + tx * 4;
        float4 s = make_float4(acc[i][0] * dv, acc[i][1] * dv,
                               acc[i][2] * dv, acc[i][3] * dv);
        *(float4*)(OutS + base) = s;
        if (MODE == 0) {
            float4 o = make_float4(acc[i][0] * dv2, acc[i][1] * dv2,
                                   acc[i][2] * dv2, acc[i][3] * dv2);
            *(float4*)(OutB + base) = o;
        } else if (MODE == 1) {
            int c = colBase + tx * 4;
            float4 b2 = *(const float4*)(bias2 + c);
            float4 b3 = *(const float4*)(bias3 + c);
            float4 o = make_float4(acc[i][0] * dv2 + b2.x + b3.x,
                                   acc[i][1] * dv2 + b2.y + b3.y,
                                   acc[i][2] * dv2 + b2.z + b3.z,
                                   acc[i][3] * dv2 + b2.w + b3.w);
            *(float4*)(OutB + base) = o;
        } else {
            float4 o = *(const float4*)(OutB + base);
            o.x += acc[i][0] * dv2; o.y += acc[i][1] * dv2;
            o.z += acc[i][2] * dv2; o.w += acc[i][3] * dv2;
            *(float4*)(OutB + base) = o;
        }
    }
}

// ---------------------------------------------------------------------------
// gather aggregation (no atomics): Acc[node] += dinv[node] * sum_{s in adj(node)} Hs[s]
// Hs is pre-scaled by dinv[src]. C4 = columns/4 (64 or 32).
// Each node is served by C4 threads; warps never span nodes.
// ---------------------------------------------------------------------------
template <int C4>
__global__ __launch_bounds__(256) void k_gather(const int* __restrict__ rowptr,
                                                const int* __restrict__ adj,
                                                const float* __restrict__ dinv,
                                                const float4* __restrict__ Hs,
                                                float4* __restrict__ Acc, int N) {
    constexpr int NPB = 256 / C4;
    int node = blockIdx.x * NPB + (threadIdx.x / C4);
    int c = threadIdx.x & (C4 - 1);
    if (node >= N) return;
    int beg = rowptr[node];
    int end = rowptr[node + 1];
    float sx = 0.f, sy = 0.f, sz = 0.f, sw = 0.f;
    int j = beg;
    for (; j + 2 <= end; j += 2) {
        int s0 = adj[j];
        int s1 = adj[j + 1];
        float4 h0 = Hs[(long long)s0 * C4 + c];
        float4 h1 = Hs[(long long)s1 * C4 + c];
        sx += h0.x + h1.x; sy += h0.y + h1.y;
        sz += h0.z + h1.z; sw += h0.w + h1.w;
    }
    if (j < end) {
        int s0 = adj[j];
        float4 h0 = Hs[(long long)s0 * C4 + c];
        sx += h0.x; sy += h0.y; sz += h0.z; sw += h0.w;
    }
    float w = dinv[node];
    float4 a = Acc[(long long)node * C4 + c];
    a.x += sx * w; a.y += sy * w; a.z += sz * w; a.w += sw * w;
    Acc[(long long)node * C4 + c] = a;
}

// ---------------------------------------------------------------------------
extern "C" void kernel_launch(void* const* d_in, const int* in_sizes, int n_in,
                              void* d_out, int out_size) {
    const float* x   = (const float*)d_in[0];
    const void*  ei  = d_in[1];
    const void*  ei2 = d_in[2];
    const float* W0 = (const float*)d_in[3];
    const float* b0 = (const float*)d_in[4];
    const float* W1 = (const float*)d_in[5];
    const float* b1 = (const float*)d_in[6];
    const float* W2 = (const float*)d_in[7];
    const float* b2 = (const float*)d_in[8];
    const float* W3 = (const float*)d_in[9];
    const float* b3 = (const float*)d_in[10];

    const int N = in_sizes[0] / 128;   // 50000
    const int E = in_sizes[1] / 2;     // 800000

    float* S = nullptr;
    cudaGetSymbolAddress((void**)&S, g_scratch);
    float* dinv1 = S + OFF_DINV1;
    float* dinv2 = S + OFF_DINV2;
    int*   cnt1  = (int*)(S + OFF_CNT1);
    int*   cnt2  = (int*)(S + OFF_CNT2);
    int*   rp1   = (int*)(S + OFF_RP1);
    int*   rp2   = (int*)(S + OFF_RP2);
    int*   fp1   = (int*)(S + OFF_FP1);
    int*   fp2   = (int*)(S + OFF_FP2);
    int*   idx1  = (int*)(S + OFF_IDX1);
    int*   idx2  = (int*)(S + OFF_IDX2);
    int*   adj1  = (int*)(S + OFF_ADJ1);
    int*   adj2  = (int*)(S + OFF_ADJ2);
    float* Hs1   = S + OFF_HS1;
    float* Hs2   = S + OFF_HS2;
    float* A1    = S + OFF_A1;
    float* A2    = S + OFF_A2;
    float* Gs1   = S + OFF_GS1;
    float* Gs2   = S + OFF_GS2;
    float* out   = (float*)d_out;

    // 0) index dtype detection + decode
    k_flag_init<<<1, 1>>>();
    k_detect<<<(E + 255) / 256, 256>>>((const long long*)ei, E, N);
    k_convert2<<<(2 * E + 255) / 256, 256>>>(ei, ei2, idx1, idx2, 2 * E);

    const int* src1 = idx1;
    const int* dst1 = idx1 + E;
    const int* src2 = idx2;
    const int* dst2 = idx2 + E;

    // 1) degrees -> dinv, and CSR build (histogram -> scan -> fill)
    k_zero_int<<<(2 * N + 255) / 256, 256>>>(cnt1, 2 * N);   // cnt1,cnt2 contiguous
    k_degi<<<(E + 255) / 256, 256>>>(dst1, dst2, cnt1, cnt2, E);
    k_dinv<<<(2 * N + 255) / 256, 256>>>(cnt1, dinv1, 2 * N); // dinv1,dinv2 contiguous
    k_scan<<<1, 1024>>>(cnt1, cnt2, rp1, rp2, fp1, fp2, N);
    k_fill2<<<(E + 255) / 256, 256>>>(src1, dst1, src2, dst2, fp1, fp2, adj1, adj2, E);

    // 2) layer-1 GEMMs with fused (scale, self-loop) epilogue
    //    Hs = (x@W)*dinv ;  A = (x@W)*dinv^2
    dim3 g1(256 / 64, (N + 127) / 128);
    k_gemm2<0><<<g1, 256>>>(x, nullptr, W0, dinv1, Hs1, A1, nullptr, nullptr, N, 128, 256);
    k_gemm2<0><<<g1, 256>>>(x, nullptr, W1, dinv2, Hs2, A2, nullptr, nullptr, N, 128, 256);

    // 3) gather aggregation (atomic-free): A[n] += dinv[n]*sum Hs[adj]
    k_gather<64><<<N / 4, 256>>>(rp1, adj1, dinv1, (const float4*)Hs1, (float4*)A1, N);
    k_gather<64><<<N / 4, 256>>>(rp2, adj2, dinv2, (const float4*)Hs2, (float4*)A2, N);

    // 4) layer-2 GEMMs: prologue relu(A+b), epilogue writes Gs and composes out
    dim3 g2(128 / 64, (N + 127) / 128);
    k_gemm2<1><<<g2, 256>>>(A1, b0, W2, dinv1, Gs1, out, b2, b3, N, 256, 128);
    k_gemm2<2><<<g2, 256>>>(A2, b1, W3, dinv2, Gs2, out, nullptr, nullptr, N, 256, 128);

    // 5) final gathers accumulate into out
    k_gather<32><<<N / 8, 256>>>(rp1, adj1, dinv1, (const float4*)Gs1, (float4*)out, N);
    k_gather<32><<<N / 8, 256>>>(rp2, adj2, dinv2, (const float4*)Gs2, (float4*)out, N);
}

// round 6
// speedup vs baseline: 2.1513x; 1.2211x over previous
#include <cuda_runtime.h>
#include <cstdint>

// Problem constants (fixed by the reference)
constexpr long long Nn = 50000;
constexpr long long Ee = 800000;
constexpr long long RP = 50008;   // rowptr stride (>= Nn+1, multiple of 4)

// Scratch layout inside one __device__ array (no allocations allowed).
constexpr long long OFF_DINV1 = 0;
constexpr long long OFF_DINV2 = OFF_DINV1 + Nn;
constexpr long long OFF_CNT1  = OFF_DINV2 + Nn;            // int
constexpr long long OFF_CNT2  = OFF_CNT1  + Nn;            // int
constexpr long long OFF_RP1   = OFF_CNT2  + Nn;            // int rowptr
constexpr long long OFF_RP2   = OFF_RP1   + RP;
constexpr long long OFF_FP1   = OFF_RP2   + RP;            // int fill cursor
constexpr long long OFF_FP2   = OFF_FP1   + Nn;
constexpr long long OFF_IDX1  = OFF_FP2   + Nn;            // src1,dst1 [2E] int
constexpr long long OFF_IDX2  = OFF_IDX1  + 2 * Ee;        // src2,dst2 [2E] int
constexpr long long OFF_ADJ1  = OFF_IDX2  + 2 * Ee;        // CSR adj   [E] int
constexpr long long OFF_ADJ2  = OFF_ADJ1  + Ee;
constexpr long long OFF_HS1   = OFF_ADJ2  + Ee;            // h0*dinv   [N,256]
constexpr long long OFF_HS2   = OFF_HS1   + Nn * 256;      // h1*dinv   [N,256]
constexpr long long OFF_A1    = OFF_HS2   + Nn * 256;      // agg1      [N,256]
constexpr long long OFF_A2    = OFF_A1    + Nn * 256;      // agg2      [N,256]
constexpr long long OFF_GS1   = OFF_A2    + Nn * 256;      // g1*dinv   [N,128]
constexpr long long OFF_GS2   = OFF_GS1   + Nn * 128;      // g2*dinv   [N,128]
constexpr long long SCRATCH   = OFF_GS2   + Nn * 128;

__device__ float g_scratch[SCRATCH];
__device__ int   g_is64;   // 1 if edge indices are int64, 0 if int32

// ---------------------------------------------------------------------------
// index dtype detection + decode (handles JAX silently downcasting int64->int32)
// ---------------------------------------------------------------------------
__global__ void k_flag_init() { g_is64 = 1; }

__global__ void k_detect(const long long* __restrict__ p, int words, int n) {
    int i = blockIdx.x * blockDim.x + threadIdx.x;
    if (i < words) {
        long long v = p[i];
        if (v < 0 || v >= n) g_is64 = 0;   // benign race: all writers write 0
    }
}

__global__ void k_convert2(const void* __restrict__ p1, const void* __restrict__ p2,
                           int* __restrict__ o1, int* __restrict__ o2, int count) {
    int i = blockIdx.x * blockDim.x + threadIdx.x;
    if (i < count) {
        if (g_is64) {
            o1[i] = (int)((const long long*)p1)[i];
            o2[i] = (int)((const long long*)p2)[i];
        } else {
            o1[i] = ((const int*)p1)[i];
            o2[i] = ((const int*)p2)[i];
        }
    }
}

// ---------------------------------------------------------------------------
// degree / dinv / CSR build
// ---------------------------------------------------------------------------
__global__ void k_zero_int(int* __restrict__ p, int n) {
    int i = blockIdx.x * blockDim.x + threadIdx.x;
    if (i < n) p[i] = 0;
}

__global__ void k_degi(const int* __restrict__ dst1, const int* __restrict__ dst2,
                       int* __restrict__ cnt1, int* __restrict__ cnt2, int E) {
    int e = blockIdx.x * blockDim.x + threadIdx.x;
    if (e < E) {
        atomicAdd(&cnt1[dst1[e]], 1);
        atomicAdd(&cnt2[dst2[e]], 1);
    }
}

__global__ void k_dinv(const int* __restrict__ cnt, float* __restrict__ dinv, int n2) {
    int i = blockIdx.x * blockDim.x + threadIdx.x;
    if (i < n2) dinv[i] = rsqrtf((float)cnt[i] + 1.0f);
}

// single-block exclusive scan (warp-shuffle based)
__device__ void scan_one(const int* __restrict__ cnt, int* __restrict__ rp,
                         int* __restrict__ fp, int n) {
    __shared__ int wsum[32];
    __shared__ int s_base;
    const int t = threadIdx.x;
    const int lane = t & 31, wid = t >> 5;
    if (t == 0) s_base = 0;
    __syncthreads();
    for (int chunk = 0; chunk < n; chunk += 1024) {
        int v = (chunk + t < n) ? cnt[chunk + t] : 0;
        int incl = v;
#pragma unroll
        for (int off = 1; off < 32; off <<= 1) {
            int x = __shfl_up_sync(0xffffffffu, incl, off);
            if (lane >= off) incl += x;
        }
        if (lane == 31) wsum[wid] = incl;
        __syncthreads();
        if (wid == 0) {
            int s = wsum[lane];
#pragma unroll
            for (int off = 1; off < 32; off <<= 1) {
                int x = __shfl_up_sync(0xffffffffu, s, off);
                if (lane >= off) s += x;
            }
            wsum[lane] = s;
        }
        __syncthreads();
        int warpoff = (wid == 0) ? 0 : wsum[wid - 1];
        int base = s_base;
        __syncthreads();
        if (chunk + t < n) {
            int ex = base + warpoff + incl - v;
            rp[chunk + t] = ex;
            fp[chunk + t] = ex;
        }
        if (t == 0) s_base = base + wsum[31];
        __syncthreads();
    }
    if (t == 0) rp[n] = s_base;
    __syncthreads();
}

__global__ void k_scan(const int* __restrict__ cnt1, const int* __restrict__ cnt2,
                       int* __restrict__ rp1, int* __restrict__ rp2,
                       int* __restrict__ fp1, int* __restrict__ fp2, int n) {
    scan_one(cnt1, rp1, fp1, n);
    scan_one(cnt2, rp2, fp2, n);
}

__global__ void k_fill2(const int* __restrict__ src1, const int* __restrict__ dst1,
                        const int* __restrict__ src2, const int* __restrict__ dst2,
                        int* __restrict__ fp1, int* __restrict__ fp2,
                        int* __restrict__ adj1, int* __restrict__ adj2, int E) {
    int e = blockIdx.x * blockDim.x + threadIdx.x;
    if (e < E) {
        int p1 = atomicAdd(&fp1[dst1[e]], 1);
        adj1[p1] = src1[e];
        int p2 = atomicAdd(&fp2[dst2[e]], 1);
        adj2[p2] = src2[e];
    }
}

// ---------------------------------------------------------------------------
// TF32 tensor-core GEMM: C = op(A[M,K]) * B[K,Ncol] with fused GCN epilogues.
//   BM=128, BN=64, BK=32. 256 threads = 8 warps (4 in M x 2 in N), warp tile
//   32x32 = 2x4 m16n8k8 mma tiles. Inputs rounded to tf32 (cvt.rna) on the
//   SMEM-store path; fp32 accumulation.
// MODE 0 (layer1):  op=identity.       epi: OutS = h*dv ; OutB  = h*dv^2
// MODE 1 (layer2a): op=relu(A+biasA).  epi: OutS = g*dv ; OutB  = g*dv^2 + b2 + b3
// MODE 2 (layer2b): op=relu(A+biasA).  epi: OutS = g*dv ; OutB += g*dv^2
// ---------------------------------------------------------------------------
__device__ __forceinline__ float to_tf32(float x) {
    uint32_t r;
    asm("cvt.rna.tf32.f32 %0, %1;" : "=r"(r) : "f"(x));
    return __uint_as_float(r);
}

__device__ __forceinline__ void mma_tf32(float* c, uint32_t a0, uint32_t a1,
                                         uint32_t a2, uint32_t a3,
                                         uint32_t b0, uint32_t b1) {
    asm volatile(
        "mma.sync.aligned.m16n8k8.row.col.f32.tf32.tf32.f32 "
        "{%0,%1,%2,%3}, {%4,%5,%6,%7}, {%8,%9}, {%0,%1,%2,%3};\n"
        : "+f"(c[0]), "+f"(c[1]), "+f"(c[2]), "+f"(c[3])
        : "r"(a0), "r"(a1), "r"(a2), "r"(a3), "r"(b0), "r"(b1));
}

template <int MODE>
__global__ __launch_bounds__(256) void k_gemm_tf32(const float* __restrict__ A,
                                                   const float* __restrict__ biasA,
                                                   const float* __restrict__ B,
                                                   const float* __restrict__ dinv,
                                                   float* __restrict__ OutS,
                                                   float* __restrict__ OutB,
                                                   const float* __restrict__ bias2,
                                                   const float* __restrict__ bias3,
                                                   int M, int K, int Ncol) {
    __shared__ float As[128 * 36];   // [m][k], pad 36 -> conflict-free frag loads
    __shared__ float Bs[32 * 64];    // [k][n], XOR swizzle n ^ ((k&3)*8)

    const int tid  = threadIdx.x;
    const int wid  = tid >> 5;
    const int lane = tid & 31;
    const int gid  = lane >> 2;     // 0..7
    const int tig  = lane & 3;      // 0..3
    const int wm   = wid >> 1;      // 0..3
    const int wn   = wid & 1;       // 0..1
    const int rowBase = blockIdx.y * 128;
    const int colBase = blockIdx.x * 64;

    float acc[2][4][4] = {};

    for (int k0 = 0; k0 < K; k0 += 32) {
        // A tile: 128 rows x 32 k = 1024 float4, 4 per thread
#pragma unroll
        for (int t = 0; t < 4; t++) {
            int idx = tid + t * 256;        // 0..1023
            int r   = idx >> 3;             // 0..127
            int q   = (idx & 7) * 4;        // 0..28
            int row = rowBase + r;
            float4 v = make_float4(0.f, 0.f, 0.f, 0.f);
            if (row < M) {
                v = *(const float4*)(A + (long long)row * K + k0 + q);
                if (MODE != 0) {
                    float4 bb = *(const float4*)(biasA + k0 + q);
                    v.x = fmaxf(v.x + bb.x, 0.f);
                    v.y = fmaxf(v.y + bb.y, 0.f);
                    v.z = fmaxf(v.z + bb.z, 0.f);
                    v.w = fmaxf(v.w + bb.w, 0.f);
                }
            }
            float4 tv = make_float4(to_tf32(v.x), to_tf32(v.y), to_tf32(v.z), to_tf32(v.w));
            *(float4*)(As + r * 36 + q) = tv;
        }
        // B tile: 32 k x 64 n = 512 float4, 2 per thread, swizzled store
#pragma unroll
        for (int t = 0; t < 2; t++) {
            int idx = tid + t * 256;        // 0..511
            int kk  = idx >> 4;             // 0..31
            int c   = (idx & 15) * 4;       // 0..60
            float4 v = *(const float4*)(B + (long long)(k0 + kk) * Ncol + colBase + c);
            float4 tv = make_float4(to_tf32(v.x), to_tf32(v.y), to_tf32(v.z), to_tf32(v.w));
            int cs = c ^ ((kk & 3) * 8);
            *(float4*)(Bs + kk * 64 + cs) = tv;
        }
        __syncthreads();

#pragma unroll
        for (int kc = 0; kc < 32; kc += 8) {
            uint32_t a[2][4];
#pragma unroll
            for (int mt = 0; mt < 2; mt++) {
                int r = wm * 32 + mt * 16;
                a[mt][0] = __float_as_uint(As[(r + gid)     * 36 + kc + tig]);
                a[mt][1] = __float_as_uint(As[(r + gid + 8) * 36 + kc + tig]);
                a[mt][2] = __float_as_uint(As[(r + gid)     * 36 + kc + tig + 4]);
                a[mt][3] = __float_as_uint(As[(r + gid + 8) * 36 + kc + tig + 4]);
            }
            uint32_t b[4][2];
#pragma unroll
            for (int nt = 0; nt < 4; nt++) {
                int n = wn * 32 + nt * 8 + gid;
                int k1 = kc + tig, k2 = kc + tig + 4;
                b[nt][0] = __float_as_uint(Bs[k1 * 64 + (n ^ ((k1 & 3) * 8))]);
                b[nt][1] = __float_as_uint(Bs[k2 * 64 + (n ^ ((k2 & 3) * 8))]);
            }
#pragma unroll
            for (int mt = 0; mt < 2; mt++)
#pragma unroll
                for (int nt = 0; nt < 4; nt++)
                    mma_tf32(acc[mt][nt], a[mt][0], a[mt][1], a[mt][2], a[mt][3],
                             b[nt][0], b[nt][1]);
        }
        __syncthreads();
    }

    // epilogue: c0,c1 -> row gid, cols 2tig,2tig+1 ; c2,c3 -> row gid+8
#pragma unroll
    for (int mt = 0; mt < 2; mt++) {
#pragma unroll
        for (int h = 0; h < 2; h++) {
            int row = rowBase + wm * 32 + mt * 16 + gid + h * 8;
            if (row >= M) continue;
            float dv  = dinv[row];
            float dv2 = dv * dv;
            long long rb = (long long)row * Ncol;
#pragma unroll
            for (int nt = 0; nt < 4; nt++) {
                int c = colBase + wn * 32 + nt * 8 + 2 * tig;
                float v0 = acc[mt][nt][2 * h + 0];
                float v1 = acc[mt][nt][2 * h + 1];
                float2 s = make_float2(v0 * dv, v1 * dv);
                *(float2*)(OutS + rb + c) = s;
                if (MODE == 0) {
                    *(float2*)(OutB + rb + c) = make_float2(v0 * dv2, v1 * dv2);
                } else if (MODE == 1) {
                    float2 p2 = *(const float2*)(bias2 + c);
                    float2 p3 = *(const float2*)(bias3 + c);
                    *(float2*)(OutB + rb + c) =
                        make_float2(v0 * dv2 + p2.x + p3.x, v1 * dv2 + p2.y + p3.y);
                } else {
                    float2 o = *(const float2*)(OutB + rb + c);
                    o.x += v0 * dv2;
                    o.y += v1 * dv2;
                    *(float2*)(OutB + rb + c) = o;
                }
            }
        }
    }
}

// ---------------------------------------------------------------------------
// gather aggregation (no atomics): Acc[node] += dinv[node] * sum_{s in adj(node)} Hs[s]
// Hs is pre-scaled by dinv[src]. C4 = columns/4 (64 or 32).
// ---------------------------------------------------------------------------
template <int C4>
__global__ __launch_bounds__(256) void k_gather(const int* __restrict__ rowptr,
                                                const int* __restrict__ adj,
                                                const float* __restrict__ dinv,
                                                const float4* __restrict__ Hs,
                                                float4* __restrict__ Acc, int N) {
    constexpr int NPB = 256 / C4;
    int node = blockIdx.x * NPB + (threadIdx.x / C4);
    int c = threadIdx.x & (C4 - 1);
    if (node >= N) return;
    int beg = rowptr[node];
    int end = rowptr[node + 1];
    float sx = 0.f, sy = 0.f, sz = 0.f, sw = 0.f;
    int j = beg;
    for (; j + 2 <= end; j += 2) {
        int s0 = adj[j];
        int s1 = adj[j + 1];
        float4 h0 = Hs[(long long)s0 * C4 + c];
        float4 h1 = Hs[(long long)s1 * C4 + c];
        sx += h0.x + h1.x; sy += h0.y + h1.y;
        sz += h0.z + h1.z; sw += h0.w + h1.w;
    }
    if (j < end) {
        int s0 = adj[j];
        float4 h0 = Hs[(long long)s0 * C4 + c];
        sx += h0.x; sy += h0.y; sz += h0.z; sw += h0.w;
    }
    float w = dinv[node];
    float4 a = Acc[(long long)node * C4 + c];
    a.x += sx * w; a.y += sy * w; a.z += sz * w; a.w += sw * w;
    Acc[(long long)node * C4 + c] = a;
}

// ---------------------------------------------------------------------------
extern "C" void kernel_launch(void* const* d_in, const int* in_sizes, int n_in,
                              void* d_out, int out_size) {
    const float* x   = (const float*)d_in[0];
    const void*  ei  = d_in[1];
    const void*  ei2 = d_in[2];
    const float* W0 = (const float*)d_in[3];
    const float* b0 = (const float*)d_in[4];
    const float* W1 = (const float*)d_in[5];
    const float* b1 = (const float*)d_in[6];
    const float* W2 = (const float*)d_in[7];
    const float* b2 = (const float*)d_in[8];
    const float* W3 = (const float*)d_in[9];
    const float* b3 = (const float*)d_in[10];

    const int N = in_sizes[0] / 128;   // 50000
    const int E = in_sizes[1] / 2;     // 800000

    float* S = nullptr;
    cudaGetSymbolAddress((void**)&S, g_scratch);
    float* dinv1 = S + OFF_DINV1;
    float* dinv2 = S + OFF_DINV2;
    int*   cnt1  = (int*)(S + OFF_CNT1);
    int*   cnt2  = (int*)(S + OFF_CNT2);
    int*   rp1   = (int*)(S + OFF_RP1);
    int*   rp2   = (int*)(S + OFF_RP2);
    int*   fp1   = (int*)(S + OFF_FP1);
    int*   fp2   = (int*)(S + OFF_FP2);
    int*   idx1  = (int*)(S + OFF_IDX1);
    int*   idx2  = (int*)(S + OFF_IDX2);
    int*   adj1  = (int*)(S + OFF_ADJ1);
    int*   adj2  = (int*)(S + OFF_ADJ2);
    float* Hs1   = S + OFF_HS1;
    float* Hs2   = S + OFF_HS2;
    float* A1    = S + OFF_A1;
    float* A2    = S + OFF_A2;
    float* Gs1   = S + OFF_GS1;
    float* Gs2   = S + OFF_GS2;
    float* out   = (float*)d_out;

    // 0) index dtype detection + decode
    k_flag_init<<<1, 1>>>();
    k_detect<<<(E + 255) / 256, 256>>>((const long long*)ei, E, N);
    k_convert2<<<(2 * E + 255) / 256, 256>>>(ei, ei2, idx1, idx2, 2 * E);

    const int* src1 = idx1;
    const int* dst1 = idx1 + E;
    const int* src2 = idx2;
    const int* dst2 = idx2 + E;

    // 1) degrees -> dinv, CSR build (histogram -> scan -> fill)
    k_zero_int<<<(2 * N + 255) / 256, 256>>>(cnt1, 2 * N);
    k_degi<<<(E + 255) / 256, 256>>>(dst1, dst2, cnt1, cnt2, E);
    k_dinv<<<(2 * N + 255) / 256, 256>>>(cnt1, dinv1, 2 * N);
    k_scan<<<1, 1024>>>(cnt1, cnt2, rp1, rp2, fp1, fp2, N);
    k_fill2<<<(E + 255) / 256, 256>>>(src1, dst1, src2, dst2, fp1, fp2, adj1, adj2, E);

    // 2) layer-1 GEMMs (tf32 tensor cores) with fused (scale, self-loop) epilogue
    dim3 g1(256 / 64, (N + 127) / 128);
    k_gemm_tf32<0><<<g1, 256>>>(x, nullptr, W0, dinv1, Hs1, A1, nullptr, nullptr, N, 128, 256);
    k_gemm_tf32<0><<<g1, 256>>>(x, nullptr, W1, dinv2, Hs2, A2, nullptr, nullptr, N, 128, 256);

    // 3) gather aggregation (atomic-free)
    k_gather<64><<<(N + 3) / 4, 256>>>(rp1, adj1, dinv1, (const float4*)Hs1, (float4*)A1, N);
    k_gather<64><<<(N + 3) / 4, 256>>>(rp2, adj2, dinv2, (const float4*)Hs2, (float4*)A2, N);

    // 4) layer-2 GEMMs: fused relu(A+b) prologue; epilogue writes Gs and composes out
    dim3 g2(128 / 64, (N + 127) / 128);
    k_gemm_tf32<1><<<g2, 256>>>(A1, b0, W2, dinv1, Gs1, out, b2, b3, N, 256, 128);
    k_gemm_tf32<2><<<g2, 256>>>(A2, b1, W3, dinv2, Gs2, out, nullptr, nullptr, N, 256, 128);

    // 5) final gathers accumulate into out
    k_gather<32><<<(N + 7) / 8, 256>>>(rp1, adj1, dinv1, (const float4*)Gs1, (float4*)out, N);
    k_gather<32><<<(N + 7) / 8, 256>>>(rp2, adj2, dinv2, (const float4*)Gs2, (float4*)out, N);
}

// round 8
// speedup vs baseline: 2.6384x; 1.2265x over previous
#include <cuda_runtime.h>
#include <cstdint>

// Problem constants (fixed by the reference)
constexpr long long Nn = 50000;
constexpr long long Ee = 800000;
constexpr long long RP = 50008;   // rowptr stride (>= Nn+1, multiple of 4)

// Scratch layout inside one __device__ array (no allocations allowed).
constexpr long long OFF_DINV1 = 0;
constexpr long long OFF_DINV2 = OFF_DINV1 + Nn;
constexpr long long OFF_CNT1  = OFF_DINV2 + Nn;            // int
constexpr long long OFF_CNT2  = OFF_CNT1  + Nn;            // int
constexpr long long OFF_RP1   = OFF_CNT2  + Nn;            // int rowptr
constexpr long long OFF_RP2   = OFF_RP1   + RP;
constexpr long long OFF_FP1   = OFF_RP2   + RP;            // int fill cursor
constexpr long long OFF_FP2   = OFF_FP1   + Nn;
constexpr long long OFF_IDX1  = OFF_FP2   + Nn;            // src1,dst1 [2E] int
constexpr long long OFF_IDX2  = OFF_IDX1  + 2 * Ee;        // src2,dst2 [2E] int
constexpr long long OFF_ADJ1  = OFF_IDX2  + 2 * Ee;        // CSR adj   [E] int
constexpr long long OFF_ADJ2  = OFF_ADJ1  + Ee;
constexpr long long OFF_XS1   = OFF_ADJ2  + Ee;            // x*dinv1   [N,128]
constexpr long long OFF_XS2   = OFF_XS1   + Nn * 128;      // x*dinv2   [N,128]
constexpr long long OFF_XA1   = OFF_XS2   + Nn * 128;      // D1~ x     [N,128]
constexpr long long OFF_XA2   = OFF_XA1   + Nn * 128;      // D2~ x     [N,128]
constexpr long long OFF_H1    = OFF_XA2   + Nn * 128;      // relu(.@W0+b0) [N,256]
constexpr long long OFF_H2    = OFF_H1    + Nn * 256;      // relu(.@W1+b1) [N,256]
constexpr long long OFF_GS1   = OFF_H2    + Nn * 256;      // (H1@W2)*dinv1 [N,128]
constexpr long long OFF_GS2   = OFF_GS1   + Nn * 128;      // (H2@W3)*dinv2 [N,128]
constexpr long long SCRATCH   = OFF_GS2   + Nn * 128;

__device__ float g_scratch[SCRATCH];
__device__ int   g_is64;   // 1 if edge indices are int64, 0 if int32

// ---------------------------------------------------------------------------
// index dtype detection + decode (handles JAX silently downcasting int64->int32)
// ---------------------------------------------------------------------------
__global__ void k_flag_init() { g_is64 = 1; }

__global__ void k_detect(const long long* __restrict__ p, int words, int n) {
    int i = blockIdx.x * blockDim.x + threadIdx.x;
    if (i < words) {
        long long v = p[i];
        if (v < 0 || v >= n) g_is64 = 0;   // benign race: all writers write 0
    }
}

// decode both graphs' index buffers; threads i < nzero also zero the degree
// counters (cnt1,cnt2 are contiguous) so no separate zero kernel is needed.
__global__ void k_convert2(const void* __restrict__ p1, const void* __restrict__ p2,
                           int* __restrict__ o1, int* __restrict__ o2, int count,
                           int* __restrict__ cnt, int nzero) {
    int i = blockIdx.x * blockDim.x + threadIdx.x;
    if (i < nzero) cnt[i] = 0;
    if (i < count) {
        if (g_is64) {
            o1[i] = (int)((const long long*)p1)[i];
            o2[i] = (int)((const long long*)p2)[i];
        } else {
            o1[i] = ((const int*)p1)[i];
            o2[i] = ((const int*)p2)[i];
        }
    }
}

// ---------------------------------------------------------------------------
// degree histogram / CSR build
// ---------------------------------------------------------------------------
__global__ void k_degi(const int* __restrict__ dst1, const int* __restrict__ dst2,
                       int* __restrict__ cnt1, int* __restrict__ cnt2, int E) {
    int e = blockIdx.x * blockDim.x + threadIdx.x;
    if (e < E) {
        atomicAdd(&cnt1[dst1[e]], 1);
        atomicAdd(&cnt2[dst2[e]], 1);
    }
}

// exclusive scan of one graph's counts (one block per graph) + dinv compute
__device__ void scan_one(const int* __restrict__ cnt, int* __restrict__ rp,
                         int* __restrict__ fp, float* __restrict__ dinv, int n) {
    __shared__ int wsum[32];
    __shared__ int s_base;
    const int t = threadIdx.x;
    const int lane = t & 31, wid = t >> 5;
    if (t == 0) s_base = 0;
    __syncthreads();
    for (int chunk = 0; chunk < n; chunk += 1024) {
        int v = (chunk + t < n) ? cnt[chunk + t] : 0;
        if (chunk + t < n) dinv[chunk + t] = rsqrtf((float)v + 1.0f);
        int incl = v;
#pragma unroll
        for (int off = 1; off < 32; off <<= 1) {
            int x = __shfl_up_sync(0xffffffffu, incl, off);
            if (lane >= off) incl += x;
        }
        if (lane == 31) wsum[wid] = incl;
        __syncthreads();
        if (wid == 0) {
            int s = wsum[lane];
#pragma unroll
            for (int off = 1; off < 32; off <<= 1) {
                int x = __shfl_up_sync(0xffffffffu, s, off);
                if (lane >= off) s += x;
            }
            wsum[lane] = s;
        }
        __syncthreads();
        int warpoff = (wid == 0) ? 0 : wsum[wid - 1];
        int base = s_base;
        __syncthreads();
        if (chunk + t < n) {
            int ex = base + warpoff + incl - v;
            rp[chunk + t] = ex;
            fp[chunk + t] = ex;
        }
        if (t == 0) s_base = base + wsum[31];
        __syncthreads();
    }
    if (t == 0) rp[n] = s_base;
}

__global__ void k_scan(const int* __restrict__ cnt1, const int* __restrict__ cnt2,
                       int* __restrict__ rp1, int* __restrict__ rp2,
                       int* __restrict__ fp1, int* __restrict__ fp2,
                       float* __restrict__ dinv1, float* __restrict__ dinv2, int n) {
    if (blockIdx.x == 0) scan_one(cnt1, rp1, fp1, dinv1, n);
    else                 scan_one(cnt2, rp2, fp2, dinv2, n);
}

__global__ void k_fill2(const int* __restrict__ src1, const int* __restrict__ dst1,
                        const int* __restrict__ src2, const int* __restrict__ dst2,
                        int* __restrict__ fp1, int* __restrict__ fp2,
                        int* __restrict__ adj1, int* __restrict__ adj2, int E) {
    int e = blockIdx.x * blockDim.x + threadIdx.x;
    if (e < E) {
        int p1 = atomicAdd(&fp1[dst1[e]], 1);
        adj1[p1] = src1[e];
        int p2 = atomicAdd(&fp2[dst2[e]], 1);
        adj2[p2] = src2[e];
    }
}

// ---------------------------------------------------------------------------
// prescale: Xs1 = x * dinv1[row], Xs2 = x * dinv2[row] (float4, 32 per row)
// ---------------------------------------------------------------------------
__global__ void k_prescale(const float4* __restrict__ x,
                           const float* __restrict__ dinv1,
                           const float* __restrict__ dinv2,
                           float4* __restrict__ Xs1, float4* __restrict__ Xs2,
                           int total4) {
    int i = blockIdx.x * blockDim.x + threadIdx.x;
    if (i < total4) {
        int row = i >> 5;    // 128 floats = 32 float4 per row
        float4 v = x[i];
        float d1 = dinv1[row], d2 = dinv2[row];
        Xs1[i] = make_float4(v.x * d1, v.y * d1, v.z * d1, v.w * d1);
        Xs2[i] = make_float4(v.x * d2, v.y * d2, v.z * d2, v.w * d2);
    }
}

// ---------------------------------------------------------------------------
// gather aggregation (no atomics), C4 = cols/4 = 32 (128 cols).
// INIT=true:  Acc[node] = Self[node]*dinv^2 + dinv * sum_{s in adj} Hs[s]
// INIT=false: Acc[node] +=                    dinv * sum_{s in adj} Hs[s]
// Hs is pre-scaled by dinv[src]. One warp per node; fully coalesced rows.
// ---------------------------------------------------------------------------
template <int C4, bool INIT>
__global__ __launch_bounds__(256) void k_gather(const int* __restrict__ rowptr,
                                                const int* __restrict__ adj,
                                                const float* __restrict__ dinv,
                                                const float4* __restrict__ Hs,
                                                const float4* __restrict__ Self,
                                                float4* __restrict__ Acc, int N) {
    constexpr int NPB = 256 / C4;
    int node = blockIdx.x * NPB + (threadIdx.x / C4);
    int c = threadIdx.x & (C4 - 1);
    if (node >= N) return;
    int beg = rowptr[node];
    int end = rowptr[node + 1];
    float sx = 0.f, sy = 0.f, sz = 0.f, sw = 0.f;
    int j = beg;
    for (; j + 2 <= end; j += 2) {
        int s0 = adj[j];
        int s1 = adj[j + 1];
        float4 h0 = Hs[(long long)s0 * C4 + c];
        float4 h1 = Hs[(long long)s1 * C4 + c];
        sx += h0.x + h1.x; sy += h0.y + h1.y;
        sz += h0.z + h1.z; sw += h0.w + h1.w;
    }
    if (j < end) {
        int s0 = adj[j];
        float4 h0 = Hs[(long long)s0 * C4 + c];
        sx += h0.x; sy += h0.y; sz += h0.z; sw += h0.w;
    }
    float w = dinv[node];
    long long p = (long long)node * C4 + c;
    float4 a;
    if (INIT) {
        float w2 = w * w;
        float4 s = Self[p];
        a = make_float4(s.x * w2, s.y * w2, s.z * w2, s.w * w2);
    } else {
        a = Acc[p];
    }
    a.x += sx * w; a.y += sy * w; a.z += sz * w; a.w += sw * w;
    Acc[p] = a;
}

// ---------------------------------------------------------------------------
// TF32 tensor-core GEMM: C = A[M,K] * B[K,Ncol] with fused GCN epilogues.
//   BM=128, BN=64, BK=32. 256 threads = 8 warps (4 in M x 2 in N), warp tile
//   32x32 = 2x4 m16n8k8 mma tiles. Inputs rounded to tf32 (cvt.rna) on the
//   SMEM-store path; fp32 accumulation.
// MODE 0 (layer1):  OutB = relu(acc + bias2[c])
// MODE 1 (layer2a): OutS = acc*dv ; OutB  = acc*dv^2 + bias2[c] + bias3[c]
// MODE 2 (layer2b): OutS = acc*dv ; OutB += acc*dv^2
// ---------------------------------------------------------------------------
__device__ __forceinline__ float to_tf32(float x) {
    uint32_t r;
    asm("cvt.rna.tf32.f32 %0, %1;" : "=r"(r) : "f"(x));
    return __uint_as_float(r);
}

__device__ __forceinline__ void mma_tf32(float* c, uint32_t a0, uint32_t a1,
                                         uint32_t a2, uint32_t a3,
                                         uint32_t b0, uint32_t b1) {
    asm volatile(
        "mma.sync.aligned.m16n8k8.row.col.f32.tf32.tf32.f32 "
        "{%0,%1,%2,%3}, {%4,%5,%6,%7}, {%8,%9}, {%0,%1,%2,%3};\n"
        : "+f"(c[0]), "+f"(c[1]), "+f"(c[2]), "+f"(c[3])
        : "r"(a0), "r"(a1), "r"(a2), "r"(a3), "r"(b0), "r"(b1));
}

template <int MODE>
__global__ __launch_bounds__(256) void k_gemm_tf32(const float* __restrict__ A,
                                                   const float* __restrict__ B,
                                                   const float* __restrict__ dinv,
                                                   float* __restrict__ OutS,
                                                   float* __restrict__ OutB,
                                                   const float* __restrict__ bias2,
                                                   const float* __restrict__ bias3,
                                                   int M, int K, int Ncol) {
    __shared__ float As[128 * 36];   // [m][k], pad 36 -> conflict-free frag loads
    __shared__ float Bs[32 * 64];    // [k][n], XOR swizzle n ^ ((k&3)*8)

    const int tid  = threadIdx.x;
    const int wid  = tid >> 5;
    const int lane = tid & 31;
    const int gid  = lane >> 2;     // 0..7
    const int tig  = lane & 3;      // 0..3
    const int wm   = wid >> 1;      // 0..3
    const int wn   = wid & 1;       // 0..1
    const int rowBase = blockIdx.y * 128;
    const int colBase = blockIdx.x * 64;

    float acc[2][4][4] = {};

    for (int k0 = 0; k0 < K; k0 += 32) {
        // A tile: 128 rows x 32 k = 1024 float4, 4 per thread
#pragma unroll
        for (int t = 0; t < 4; t++) {
            int idx = tid + t * 256;        // 0..1023
            int r   = idx >> 3;             // 0..127
            int q   = (idx & 7) * 4;        // 0..28
            int row = rowBase + r;
            float4 v = make_float4(0.f, 0.f, 0.f, 0.f);
            if (row < M) v = *(const float4*)(A + (long long)row * K + k0 + q);
            float4 tv = make_float4(to_tf32(v.x), to_tf32(v.y), to_tf32(v.z), to_tf32(v.w));
            *(float4*)(As + r * 36 + q) = tv;
        }
        // B tile: 32 k x 64 n = 512 float4, 2 per thread, swizzled store
#pragma unroll
        for (int t = 0; t < 2; t++) {
            int idx = tid + t * 256;        // 0..511
            int kk  = idx >> 4;             // 0..31
            int c   = (idx & 15) * 4;       // 0..60
            float4 v = *(const float4*)(B + (long long)(k0 + kk) * Ncol + colBase + c);
            float4 tv = make_float4(to_tf32(v.x), to_tf32(v.y), to_tf32(v.z), to_tf32(v.w));
            int cs = c ^ ((kk & 3) * 8);
            *(float4*)(Bs + kk * 64 + cs) = tv;
        }
        __syncthreads();

#pragma unroll
        for (int kc = 0; kc < 32; kc += 8) {
            uint32_t a[2][4];
#pragma unroll
            for (int mt = 0; mt < 2; mt++) {
                int r = wm * 32 + mt * 16;
                a[mt][0] = __float_as_uint(As[(r + gid)     * 36 + kc + tig]);
                a[mt][1] = __float_as_uint(As[(r + gid + 8) * 36 + kc + tig]);
                a[mt][2] = __float_as_uint(As[(r + gid)     * 36 + kc + tig + 4]);
                a[mt][3] = __float_as_uint(As[(r + gid + 8) * 36 + kc + tig + 4]);
            }
            uint32_t b[4][2];
#pragma unroll
            for (int nt = 0; nt < 4; nt++) {
                int n = wn * 32 + nt * 8 + gid;
                int k1 = kc + tig, k2 = kc + tig + 4;
                b[nt][0] = __float_as_uint(Bs[k1 * 64 + (n ^ ((k1 & 3) * 8))]);
                b[nt][1] = __float_as_uint(Bs[k2 * 64 + (n ^ ((k2 & 3) * 8))]);
            }
#pragma unroll
            for (int mt = 0; mt < 2; mt++)
#pragma unroll
                for (int nt = 0; nt < 4; nt++)
                    mma_tf32(acc[mt][nt], a[mt][0], a[mt][1], a[mt][2], a[mt][3],
                             b[nt][0], b[nt][1]);
        }
        __syncthreads();
    }

    // epilogue: c0,c1 -> row gid, cols 2tig,2tig+1 ; c2,c3 -> row gid+8
#pragma unroll
    for (int mt = 0; mt < 2; mt++) {
#pragma unroll
        for (int h = 0; h < 2; h++) {
            int row = rowBase + wm * 32 + mt * 16 + gid + h * 8;
            if (row >= M) continue;
            float dv  = (MODE == 0) ? 0.f : dinv[row];
            float dv2 = dv * dv;
            long long rb = (long long)row * Ncol;
#pragma unroll
            for (int nt = 0; nt < 4; nt++) {
                int c = colBase + wn * 32 + nt * 8 + 2 * tig;
                float v0 = acc[mt][nt][2 * h + 0];
                float v1 = acc[mt][nt][2 * h + 1];
                if (MODE == 0) {
                    float2 bb = *(const float2*)(bias2 + c);
                    *(float2*)(OutB + rb + c) =
                        make_float2(fmaxf(v0 + bb.x, 0.f), fmaxf(v1 + bb.y, 0.f));
                } else if (MODE == 1) {
                    *(float2*)(OutS + rb + c) = make_float2(v0 * dv, v1 * dv);
                    float2 p2 = *(const float2*)(bias2 + c);
                    float2 p3 = *(const float2*)(bias3 + c);
                    *(float2*)(OutB + rb + c) =
                        make_float2(v0 * dv2 + p2.x + p3.x, v1 * dv2 + p2.y + p3.y);
                } else {
                    *(float2*)(OutS + rb + c) = make_float2(v0 * dv, v1 * dv);
                    float2 o = *(const float2*)(OutB + rb + c);
                    o.x += v0 * dv2;
                    o.y += v1 * dv2;
                    *(float2*)(OutB + rb + c) = o;
                }
            }
        }
    }
}

// ---------------------------------------------------------------------------
extern "C" void kernel_launch(void* const* d_in, const int* in_sizes, int n_in,
                              void* d_out, int out_size) {
    const float* x   = (const float*)d_in[0];
    const void*  ei  = d_in[1];
    const void*  ei2 = d_in[2];
    const float* W0 = (const float*)d_in[3];
    const float* b0 = (const float*)d_in[4];
    const float* W1 = (const float*)d_in[5];
    const float* b1 = (const float*)d_in[6];
    const float* W2 = (const float*)d_in[7];
    const float* b2 = (const float*)d_in[8];
    const float* W3 = (const float*)d_in[9];
    const float* b3 = (const float*)d_in[10];

    const int N = in_sizes[0] / 128;   // 50000
    const int E = in_sizes[1] / 2;     // 800000

    float* S = nullptr;
    cudaGetSymbolAddress((void**)&S, g_scratch);
    float* dinv1 = S + OFF_DINV1;
    float* dinv2 = S + OFF_DINV2;
    int*   cnt1  = (int*)(S + OFF_CNT1);
    int*   cnt2  = (int*)(S + OFF_CNT2);
    int*   rp1   = (int*)(S + OFF_RP1);
    int*   rp2   = (int*)(S + OFF_RP2);
    int*   fp1   = (int*)(S + OFF_FP1);
    int*   fp2   = (int*)(S + OFF_FP2);
    int*   idx1  = (int*)(S + OFF_IDX1);
    int*   idx2  = (int*)(S + OFF_IDX2);
    int*   adj1  = (int*)(S + OFF_ADJ1);
    int*   adj2  = (int*)(S + OFF_ADJ2);
    float* Xs1   = S + OFF_XS1;
    float* Xs2   = S + OFF_XS2;
    float* Xa1   = S + OFF_XA1;
    float* Xa2   = S + OFF_XA2;
    float* H1    = S + OFF_H1;
    float* H2    = S + OFF_H2;
    float* Gs1   = S + OFF_GS1;
    float* Gs2   = S + OFF_GS2;
    float* out   = (float*)d_out;

    // 0) index dtype detection + decode (+ zero degree counters)
    k_flag_init<<<1, 1>>>();
    k_detect<<<(E + 255) / 256, 256>>>((const long long*)ei, E, N);
    k_convert2<<<(2 * E + 255) / 256, 256>>>(ei, ei2, idx1, idx2, 2 * E, cnt1, 2 * N);

    const int* src1 = idx1;
    const int* dst1 = idx1 + E;
    const int* src2 = idx2;
    const int* dst2 = idx2 + E;

    // 1) degree histogram -> scan (rowptr + dinv) -> CSR fill
    k_degi<<<(E + 255) / 256, 256>>>(dst1, dst2, cnt1, cnt2, E);
    k_scan<<<2, 1024>>>(cnt1, cnt2, rp1, rp2, fp1, fp2, dinv1, dinv2, N);
    k_fill2<<<(E + 255) / 256, 256>>>(src1, dst1, src2, dst2, fp1, fp2, adj1, adj2, E);

    // 2) prescale x by dinv[src] for both graphs (one read of x)
    k_prescale<<<(N * 32 + 255) / 256, 256>>>((const float4*)x, dinv1, dinv2,
                                              (float4*)Xs1, (float4*)Xs2, N * 32);

    // 3) aggregate-first on the 128-col input: Xa = x*dinv^2 + dinv * sum Xs[adj]
    k_gather<32, true><<<(N + 7) / 8, 256>>>(rp1, adj1, dinv1, (const float4*)Xs1,
                                             (const float4*)x, (float4*)Xa1, N);
    k_gather<32, true><<<(N + 7) / 8, 256>>>(rp2, adj2, dinv2, (const float4*)Xs2,
                                             (const float4*)x, (float4*)Xa2, N);

    // 4) layer-1 GEMMs: H = relu(Xa @ W + b)   (M=N, K=128, Ncol=256)
    dim3 g1(256 / 64, (N + 127) / 128);
    k_gemm_tf32<0><<<g1, 256>>>(Xa1, W0, nullptr, nullptr, H1, b0, nullptr, N, 128, 256);
    k_gemm_tf32<0><<<g1, 256>>>(Xa2, W1, nullptr, nullptr, H2, b1, nullptr, N, 128, 256);

    // 5) layer-2 GEMMs: Gs = (H@W)*dinv ; out = sum of self terms + biases
    dim3 g2(128 / 64, (N + 127) / 128);
    k_gemm_tf32<1><<<g2, 256>>>(H1, W2, dinv1, Gs1, out, b2, b3, N, 256, 128);
    k_gemm_tf32<2><<<g2, 256>>>(H2, W3, dinv2, Gs2, out, nullptr, nullptr, N, 256, 128);

    // 6) final gathers accumulate into out
    k_gather<32, false><<<(N + 7) / 8, 256>>>(rp1, adj1, dinv1, (const float4*)Gs1,
                                              nullptr, (float4*)out, N);
    k_gather<32, false><<<(N + 7) / 8, 256>>>(rp2, adj2, dinv2, (const float4*)Gs2,
                                              nullptr, (float4*)out, N);
}

// round 9
// speedup vs baseline: 3.1142x; 1.1803x over previous
#include <cuda_runtime.h>
#include <cstdint>

// Problem constants (fixed by the reference)
constexpr long long Nn = 50000;
constexpr long long Ee = 800000;
constexpr long long RP = 50008;   // rowptr stride (>= Nn+1, multiple of 4)

// Scratch layout inside one __device__ array (no allocations allowed).
constexpr long long OFF_DINV1 = 0;
constexpr long long OFF_DINV2 = OFF_DINV1 + Nn;
constexpr long long OFF_CNT1  = OFF_DINV2 + Nn;            // int
constexpr long long OFF_CNT2  = OFF_CNT1  + Nn;            // int
constexpr long long OFF_RP1   = OFF_CNT2  + Nn;            // int rowptr
constexpr long long OFF_RP2   = OFF_RP1   + RP;
constexpr long long OFF_FP1   = OFF_RP2   + RP;            // int fill cursor
constexpr long long OFF_FP2   = OFF_FP1   + Nn;
constexpr long long OFF_IDX1  = OFF_FP2   + Nn;            // src1,dst1 [2E] int
constexpr long long OFF_IDX2  = OFF_IDX1  + 2 * Ee;        // src2,dst2 [2E] int
constexpr long long OFF_ADJ1  = OFF_IDX2  + 2 * Ee;        // CSR adj   [E] int
constexpr long long OFF_ADJ2  = OFF_ADJ1  + Ee;
constexpr long long OFF_XS1   = OFF_ADJ2  + Ee;            // x*dinv1   [N,128]
constexpr long long OFF_XS2   = OFF_XS1   + Nn * 128;      // x*dinv2   [N,128]
constexpr long long OFF_XA1   = OFF_XS2   + Nn * 128;      // D1~ x     [N,128]
constexpr long long OFF_XA2   = OFF_XA1   + Nn * 128;      // D2~ x     [N,128]
constexpr long long OFF_H1    = OFF_XA2   + Nn * 128;      // relu(.@W0+b0) [N,256]
constexpr long long OFF_H2    = OFF_H1    + Nn * 256;      // relu(.@W1+b1) [N,256]
constexpr long long OFF_GS1   = OFF_H2    + Nn * 256;      // (H1@W2)*dinv1 [N,128]
constexpr long long OFF_GS2   = OFF_GS1   + Nn * 128;      // (H2@W3)*dinv2 [N,128]
constexpr long long OFF_T1    = OFF_GS2   + Nn * 128;      // gathered graph1 term [N,128]
constexpr long long SCRATCH   = OFF_T1    + Nn * 128;

__device__ float g_scratch[SCRATCH];
__device__ int   g_is64;   // 1 if edge indices are int64, 0 if int32

// ---------------------------------------------------------------------------
// index dtype detection + decode (handles JAX silently downcasting int64->int32)
// ---------------------------------------------------------------------------
__global__ void k_flag_init() { g_is64 = 1; }

__global__ void k_detect(const long long* __restrict__ p, int words, int n) {
    int i = blockIdx.x * blockDim.x + threadIdx.x;
    if (i < words) {
        long long v = p[i];
        if (v < 0 || v >= n) g_is64 = 0;   // benign race: all writers write 0
    }
}

// decode both graphs' index buffers; threads i < nzero also zero the degree
// counters (cnt1,cnt2 contiguous) so no separate zero kernel is needed.
__global__ void k_convert2(const void* __restrict__ p1, const void* __restrict__ p2,
                           int* __restrict__ o1, int* __restrict__ o2, int count,
                           int* __restrict__ cnt, int nzero) {
    int i = blockIdx.x * blockDim.x + threadIdx.x;
    if (i < nzero) cnt[i] = 0;
    if (i < count) {
        if (g_is64) {
            o1[i] = (int)((const long long*)p1)[i];
            o2[i] = (int)((const long long*)p2)[i];
        } else {
            o1[i] = ((const int*)p1)[i];
            o2[i] = ((const int*)p2)[i];
        }
    }
}

// ---------------------------------------------------------------------------
// per-graph degree histogram / CSR build (split so the two graphs can run on
// different streams)
// ---------------------------------------------------------------------------
__global__ void k_deg1(const int* __restrict__ dst, int* __restrict__ cnt, int E) {
    int e = blockIdx.x * blockDim.x + threadIdx.x;
    if (e < E) atomicAdd(&cnt[dst[e]], 1);
}

// exclusive scan of one graph's counts (single block) + dinv compute
__global__ void k_scan1(const int* __restrict__ cnt, int* __restrict__ rp,
                        int* __restrict__ fp, float* __restrict__ dinv, int n) {
    __shared__ int wsum[32];
    __shared__ int s_base;
    const int t = threadIdx.x;
    const int lane = t & 31, wid = t >> 5;
    if (t == 0) s_base = 0;
    __syncthreads();
    for (int chunk = 0; chunk < n; chunk += 1024) {
        int v = (chunk + t < n) ? cnt[chunk + t] : 0;
        if (chunk + t < n) dinv[chunk + t] = rsqrtf((float)v + 1.0f);
        int incl = v;
#pragma unroll
        for (int off = 1; off < 32; off <<= 1) {
            int x = __shfl_up_sync(0xffffffffu, incl, off);
            if (lane >= off) incl += x;
        }
        if (lane == 31) wsum[wid] = incl;
        __syncthreads();
        if (wid == 0) {
            int s = wsum[lane];
#pragma unroll
            for (int off = 1; off < 32; off <<= 1) {
                int x = __shfl_up_sync(0xffffffffu, s, off);
                if (lane >= off) s += x;
            }
            wsum[lane] = s;
        }
        __syncthreads();
        int warpoff = (wid == 0) ? 0 : wsum[wid - 1];
        int base = s_base;
        __syncthreads();
        if (chunk + t < n) {
            int ex = base + warpoff + incl - v;
            rp[chunk + t] = ex;
            fp[chunk + t] = ex;
        }
        if (t == 0) s_base = base + wsum[31];
        __syncthreads();
    }
    if (t == 0) rp[n] = s_base;
}

__global__ void k_fill1(const int* __restrict__ src, const int* __restrict__ dst,
                        int* __restrict__ fp, int* __restrict__ adj, int E) {
    int e = blockIdx.x * blockDim.x + threadIdx.x;
    if (e < E) {
        int p = atomicAdd(&fp[dst[e]], 1);
        adj[p] = src[e];
    }
}

// prescale (one graph): Xs = x * dinv[row] (float4, 32 per row)
__global__ void k_prescale1(const float4* __restrict__ x, const float* __restrict__ dinv,
                            float4* __restrict__ Xs, int total4) {
    int i = blockIdx.x * blockDim.x + threadIdx.x;
    if (i < total4) {
        int row = i >> 5;
        float4 v = x[i];
        float d = dinv[row];
        Xs[i] = make_float4(v.x * d, v.y * d, v.z * d, v.w * d);
    }
}

// out += T (float4)
__global__ void k_add(float4* __restrict__ out, const float4* __restrict__ t, int n4) {
    int i = blockIdx.x * blockDim.x + threadIdx.x;
    if (i < n4) {
        float4 o = out[i];
        float4 v = t[i];
        o.x += v.x; o.y += v.y; o.z += v.z; o.w += v.w;
        out[i] = o;
    }
}

// ---------------------------------------------------------------------------
// gather aggregation (no atomics), C4 = cols/4 = 32 (128 cols).
// GM=0 (INIT):  Acc[node] = Self[node]*dinv^2 + dinv * sum_{s in adj} Hs[s]
// GM=1 (ACC):   Acc[node] +=                    dinv * sum_{s in adj} Hs[s]
// GM=2 (WRITE): Acc[node] =                     dinv * sum_{s in adj} Hs[s]
// Hs is pre-scaled by dinv[src]. One warp per node; fully coalesced rows.
// ---------------------------------------------------------------------------
template <int C4, int GM>
__global__ __launch_bounds__(256) void k_gather(const int* __restrict__ rowptr,
                                                const int* __restrict__ adj,
                                                const float* __restrict__ dinv,
                                                const float4* __restrict__ Hs,
                                                const float4* __restrict__ Self,
                                                float4* __restrict__ Acc, int N) {
    constexpr int NPB = 256 / C4;
    int node = blockIdx.x * NPB + (threadIdx.x / C4);
    int c = threadIdx.x & (C4 - 1);
    if (node >= N) return;
    int beg = rowptr[node];
    int end = rowptr[node + 1];
    float sx = 0.f, sy = 0.f, sz = 0.f, sw = 0.f;
    int j = beg;
    for (; j + 2 <= end; j += 2) {
        int s0 = adj[j];
        int s1 = adj[j + 1];
        float4 h0 = Hs[(long long)s0 * C4 + c];
        float4 h1 = Hs[(long long)s1 * C4 + c];
        sx += h0.x + h1.x; sy += h0.y + h1.y;
        sz += h0.z + h1.z; sw += h0.w + h1.w;
    }
    if (j < end) {
        int s0 = adj[j];
        float4 h0 = Hs[(long long)s0 * C4 + c];
        sx += h0.x; sy += h0.y; sz += h0.z; sw += h0.w;
    }
    float w = dinv[node];
    long long p = (long long)node * C4 + c;
    float4 a;
    if (GM == 0) {
        float w2 = w * w;
        float4 s = Self[p];
        a = make_float4(s.x * w2, s.y * w2, s.z * w2, s.w * w2);
    } else if (GM == 1) {
        a = Acc[p];
    } else {
        a = make_float4(0.f, 0.f, 0.f, 0.f);
    }
    a.x += sx * w; a.y += sy * w; a.z += sz * w; a.w += sw * w;
    Acc[p] = a;
}

// ---------------------------------------------------------------------------
// TF32 tensor-core GEMM with cp.async double buffering.
//   C = A[M,KT] * B[KT,Ncol]; BM=128, BN=64, BK=32; 256 threads = 8 warps
//   (4 M x 2 N), warp tile 32x32 = 2x4 m16n8k8. SMEM holds raw fp32 (LDGSTS);
//   tf32 round-to-nearest (cvt.rna) applied at fragment load. fp32 accum.
// MODE 0 (layer1):  OutB = relu(acc + bias2[c])
// MODE 1 (layer2a): OutS = acc*dv ; OutB  = acc*dv^2 + bias2[c] + bias3[c]
// MODE 2 (layer2b): OutS = acc*dv ; OutB += acc*dv^2
// ---------------------------------------------------------------------------
__device__ __forceinline__ float to_tf32(float x) {
    uint32_t r;
    asm("cvt.rna.tf32.f32 %0, %1;" : "=r"(r) : "f"(x));
    return __uint_as_float(r);
}

__device__ __forceinline__ void mma_tf32(float* c, uint32_t a0, uint32_t a1,
                                         uint32_t a2, uint32_t a3,
                                         uint32_t b0, uint32_t b1) {
    asm volatile(
        "mma.sync.aligned.m16n8k8.row.col.f32.tf32.tf32.f32 "
        "{%0,%1,%2,%3}, {%4,%5,%6,%7}, {%8,%9}, {%0,%1,%2,%3};\n"
        : "+f"(c[0]), "+f"(c[1]), "+f"(c[2]), "+f"(c[3])
        : "r"(a0), "r"(a1), "r"(a2), "r"(a3), "r"(b0), "r"(b1));
}

__device__ __forceinline__ uint32_t smem_u32(const void* p) {
    return (uint32_t)__cvta_generic_to_shared(p);
}
__device__ __forceinline__ void cp16(uint32_t dst, const void* src, int sz) {
    asm volatile("cp.async.cg.shared.global [%0], [%1], 16, %2;\n"
                 :: "r"(dst), "l"(src), "r"(sz));
}
__device__ __forceinline__ void cp_commit() {
    asm volatile("cp.async.commit_group;\n");
}
template <int N_> __device__ __forceinline__ void cp_wait() {
    asm volatile("cp.async.wait_group %0;\n" :: "n"(N_));
}

template <int MODE, int KT>
__global__ __launch_bounds__(256) void k_gemm_tf32(const float* __restrict__ A,
                                                   const float* __restrict__ B,
                                                   const float* __restrict__ dinv,
                                                   float* __restrict__ OutS,
                                                   float* __restrict__ OutB,
                                                   const float* __restrict__ bias2,
                                                   const float* __restrict__ bias3,
                                                   int M, int Ncol) {
    // As: [buf][r*32 + (k ^ ((r&7)*4))]  (XOR swizzle, conflict-free ld + st)
    // Bs: [buf][k*64 + (n ^ ((k&3)*8))]
    __shared__ float As[2][128 * 32];   // 2 x 16KB
    __shared__ float Bs[2][32 * 64];    // 2 x 8KB   -> 48KB total

    const int tid  = threadIdx.x;
    const int wid  = tid >> 5;
    const int lane = tid & 31;
    const int gid  = lane >> 2;     // 0..7
    const int tig  = lane & 3;      // 0..3
    const int wm   = wid >> 1;      // 0..3
    const int wn   = wid & 1;       // 0..1
    const int rowBase = blockIdx.y * 128;
    const int colBase = blockIdx.x * 64;
    constexpr int NK = KT / 32;

    auto loadTiles = [&](int i) {
        int k0 = i * 32;
        int buf = i & 1;
#pragma unroll
        for (int t = 0; t < 4; t++) {
            int idx = tid + t * 256;        // 0..1023
            int r   = idx >> 3;             // 0..127
            int q   = (idx & 7) * 4;        // 0..28
            int row = rowBase + r;
            const float* g = A + (long long)(row < M ? row : 0) * KT + k0 + q;
            cp16(smem_u32(&As[buf][r * 32 + (q ^ ((r & 7) * 4))]), g, row < M ? 16 : 0);
        }
#pragma unroll
        for (int t = 0; t < 2; t++) {
            int idx = tid + t * 256;        // 0..511
            int kk  = idx >> 4;             // 0..31
            int c   = (idx & 15) * 4;       // 0..60
            const float* g = B + (long long)(k0 + kk) * Ncol + colBase + c;
            cp16(smem_u32(&Bs[buf][kk * 64 + (c ^ ((kk & 3) * 8))]), g, 16);
        }
        cp_commit();
    };

    float acc[2][4][4] = {};
    loadTiles(0);

#pragma unroll
    for (int i = 0; i < NK; i++) {
        if (i + 1 < NK) loadTiles(i + 1);
        if (i + 1 < NK) cp_wait<1>(); else cp_wait<0>();
        __syncthreads();

        const float* as = As[i & 1];
        const float* bs = Bs[i & 1];
#pragma unroll
        for (int kc = 0; kc < 32; kc += 8) {
            const int sa  = gid * 4;
            const int k1  = kc + tig;
            const int k2  = kc + tig + 4;
            const int k1s = k1 ^ sa;
            const int k2s = k2 ^ sa;
            uint32_t a[2][4];
#pragma unroll
            for (int mt = 0; mt < 2; mt++) {
                int r = wm * 32 + mt * 16 + gid;
                a[mt][0] = __float_as_uint(to_tf32(as[r * 32 + k1s]));
                a[mt][1] = __float_as_uint(to_tf32(as[(r + 8) * 32 + k1s]));
                a[mt][2] = __float_as_uint(to_tf32(as[r * 32 + k2s]));
                a[mt][3] = __float_as_uint(to_tf32(as[(r + 8) * 32 + k2s]));
            }
            uint32_t b[4][2];
#pragma unroll
            for (int nt = 0; nt < 4; nt++) {
                int n = wn * 32 + nt * 8 + gid;
                b[nt][0] = __float_as_uint(to_tf32(bs[k1 * 64 + (n ^ ((k1 & 3) * 8))]));
                b[nt][1] = __float_as_uint(to_tf32(bs[k2 * 64 + (n ^ ((k2 & 3) * 8))]));
            }
#pragma unroll
            for (int mt = 0; mt < 2; mt++)
#pragma unroll
                for (int nt = 0; nt < 4; nt++)
                    mma_tf32(acc[mt][nt], a[mt][0], a[mt][1], a[mt][2], a[mt][3],
                             b[nt][0], b[nt][1]);
        }
        __syncthreads();
    }

    // epilogue: c0,c1 -> row gid, cols 2tig,2tig+1 ; c2,c3 -> row gid+8
#pragma unroll
    for (int mt = 0; mt < 2; mt++) {
#pragma unroll
        for (int h = 0; h < 2; h++) {
            int row = rowBase + wm * 32 + mt * 16 + gid + h * 8;
            if (row >= M) continue;
            float dv  = (MODE == 0) ? 0.f : dinv[row];
            float dv2 = dv * dv;
            long long rb = (long long)row * Ncol;
#pragma unroll
            for (int nt = 0; nt < 4; nt++) {
                int c = colBase + wn * 32 + nt * 8 + 2 * tig;
                float v0 = acc[mt][nt][2 * h + 0];
                float v1 = acc[mt][nt][2 * h + 1];
                if (MODE == 0) {
                    float2 bb = *(const float2*)(bias2 + c);
                    *(float2*)(OutB + rb + c) =
                        make_float2(fmaxf(v0 + bb.x, 0.f), fmaxf(v1 + bb.y, 0.f));
                } else if (MODE == 1) {
                    *(float2*)(OutS + rb + c) = make_float2(v0 * dv, v1 * dv);
                    float2 p2 = *(const float2*)(bias2 + c);
                    float2 p3 = *(const float2*)(bias3 + c);
                    *(float2*)(OutB + rb + c) =
                        make_float2(v0 * dv2 + p2.x + p3.x, v1 * dv2 + p2.y + p3.y);
                } else {
                    *(float2*)(OutS + rb + c) = make_float2(v0 * dv, v1 * dv);
                    float2 o = *(const float2*)(OutB + rb + c);
                    o.x += v0 * dv2;
                    o.y += v1 * dv2;
                    *(float2*)(OutB + rb + c) = o;
                }
            }
        }
    }
}

// ---------------------------------------------------------------------------
// host side: two-stream overlapped schedule (graph-capture-legal fork/join)
// ---------------------------------------------------------------------------
static cudaStream_t g_s2   = nullptr;
static cudaEvent_t  g_evC  = nullptr;   // after index convert (fork point)
static cudaEvent_t  g_evX1 = nullptr;   // after gather Xa1 (stagger gate)
static cudaEvent_t  g_evH2 = nullptr;   // after GEMM H2 (s2)
static cudaEvent_t  g_evM1 = nullptr;   // after GEMM MODE1 (s0)
static cudaEvent_t  g_evT1 = nullptr;   // after gather T1 (s2, join point)

extern "C" void kernel_launch(void* const* d_in, const int* in_sizes, int n_in,
                              void* d_out, int out_size) {
    if (!g_s2) {   // one-time infra (no device memory involved)
        cudaStreamCreateWithFlags(&g_s2, cudaStreamNonBlocking);
        cudaEventCreateWithFlags(&g_evC,  cudaEventDisableTiming);
        cudaEventCreateWithFlags(&g_evX1, cudaEventDisableTiming);
        cudaEventCreateWithFlags(&g_evH2, cudaEventDisableTiming);
        cudaEventCreateWithFlags(&g_evM1, cudaEventDisableTiming);
        cudaEventCreateWithFlags(&g_evT1, cudaEventDisableTiming);
    }

    const float* x   = (const float*)d_in[0];
    const void*  ei  = d_in[1];
    const void*  ei2 = d_in[2];
    const float* W0 = (const float*)d_in[3];
    const float* b0 = (const float*)d_in[4];
    const float* W1 = (const float*)d_in[5];
    const float* b1 = (const float*)d_in[6];
    const float* W2 = (const float*)d_in[7];
    const float* b2 = (const float*)d_in[8];
    const float* W3 = (const float*)d_in[9];
    const float* b3 = (const float*)d_in[10];

    const int N = in_sizes[0] / 128;   // 50000
    const int E = in_sizes[1] / 2;     // 800000

    float* S = nullptr;
    cudaGetSymbolAddress((void**)&S, g_scratch);
    float* dinv1 = S + OFF_DINV1;
    float* dinv2 = S + OFF_DINV2;
    int*   cnt1  = (int*)(S + OFF_CNT1);
    int*   cnt2  = (int*)(S + OFF_CNT2);
    int*   rp1   = (int*)(S + OFF_RP1);
    int*   rp2   = (int*)(S + OFF_RP2);
    int*   fp1   = (int*)(S + OFF_FP1);
    int*   fp2   = (int*)(S + OFF_FP2);
    int*   idx1  = (int*)(S + OFF_IDX1);
    int*   idx2  = (int*)(S + OFF_IDX2);
    int*   adj1  = (int*)(S + OFF_ADJ1);
    int*   adj2  = (int*)(S + OFF_ADJ2);
    float* Xs1   = S + OFF_XS1;
    float* Xs2   = S + OFF_XS2;
    float* Xa1   = S + OFF_XA1;
    float* Xa2   = S + OFF_XA2;
    float* H1    = S + OFF_H1;
    float* H2    = S + OFF_H2;
    float* Gs1   = S + OFF_GS1;
    float* Gs2   = S + OFF_GS2;
    float* T1    = S + OFF_T1;
    float* out   = (float*)d_out;

    cudaStream_t s0 = 0;         // harness's captured default stream
    cudaStream_t s2 = g_s2;

    // ---- shared prelim (s0): dtype probe + decode (+ zero both counters)
    k_flag_init<<<1, 1, 0, s0>>>();
    k_detect<<<(E + 255) / 256, 256, 0, s0>>>((const long long*)ei, E, N);
    k_convert2<<<(2 * E + 255) / 256, 256, 0, s0>>>(ei, ei2, idx1, idx2, 2 * E, cnt1, 2 * N);
    cudaEventRecord(g_evC, s0);

    const int* src1 = idx1;
    const int* dst1 = idx1 + E;
    const int* src2 = idx2;
    const int* dst2 = idx2 + E;

    // ---- graph-1 chain on s0
    k_deg1<<<(E + 255) / 256, 256, 0, s0>>>(dst1, cnt1, E);
    k_scan1<<<1, 1024, 0, s0>>>(cnt1, rp1, fp1, dinv1, N);
    k_fill1<<<(E + 255) / 256, 256, 0, s0>>>(src1, dst1, fp1, adj1, E);
    k_prescale1<<<(N * 32 + 255) / 256, 256, 0, s0>>>((const float4*)x, dinv1, (float4*)Xs1, N * 32);
    k_gather<32, 0><<<(N + 7) / 8, 256, 0, s0>>>(rp1, adj1, dinv1, (const float4*)Xs1,
                                                 (const float4*)x, (float4*)Xa1, N);
    cudaEventRecord(g_evX1, s0);

    // ---- graph-2 chain on s2 (prelim concurrent; gather staggered after Xa1)
    cudaStreamWaitEvent(s2, g_evC, 0);
    k_deg1<<<(E + 255) / 256, 256, 0, s2>>>(dst2, cnt2, E);
    k_scan1<<<1, 1024, 0, s2>>>(cnt2, rp2, fp2, dinv2, N);
    k_fill1<<<(E + 255) / 256, 256, 0, s2>>>(src2, dst2, fp2, adj2, E);
    k_prescale1<<<(N * 32 + 255) / 256, 256, 0, s2>>>((const float4*)x, dinv2, (float4*)Xs2, N * 32);
    cudaStreamWaitEvent(s2, g_evX1, 0);
    k_gather<32, 0><<<(N + 7) / 8, 256, 0, s2>>>(rp2, adj2, dinv2, (const float4*)Xs2,
                                                 (const float4*)x, (float4*)Xa2, N);

    // ---- layer-1 GEMMs: H = relu(Xa @ W + b)  (K=128, Ncol=256)
    dim3 g1(4, (N + 127) / 128);
    k_gemm_tf32<0, 128><<<g1, 256, 0, s0>>>(Xa1, W0, nullptr, nullptr, H1, b0, nullptr, N, 256);
    k_gemm_tf32<0, 128><<<g1, 256, 0, s2>>>(Xa2, W1, nullptr, nullptr, H2, b1, nullptr, N, 256);
    cudaEventRecord(g_evH2, s2);

    // ---- layer-2 GEMMs (K=256, Ncol=128): Gs = (H@W)*dinv ; out composed
    dim3 g2(2, (N + 127) / 128);
    k_gemm_tf32<1, 256><<<g2, 256, 0, s0>>>(H1, W2, dinv1, Gs1, out, b2, b3, N, 128);
    cudaEventRecord(g_evM1, s0);

    // graph-1 output gather into T1 on s2, hidden under MODE2
    cudaStreamWaitEvent(s2, g_evM1, 0);
    k_gather<32, 2><<<(N + 7) / 8, 256, 0, s2>>>(rp1, adj1, dinv1, (const float4*)Gs1,
                                                 nullptr, (float4*)T1, N);
    cudaEventRecord(g_evT1, s2);

    cudaStreamWaitEvent(s0, g_evH2, 0);
    k_gemm_tf32<2, 256><<<g2, 256, 0, s0>>>(H2, W3, dinv2, Gs2, out, nullptr, nullptr, N, 128);

    // ---- graph-2 output gather accumulates into out, then add T1 (join)
    k_gather<32, 1><<<(N + 7) / 8, 256, 0, s0>>>(rp2, adj2, dinv2, (const float4*)Gs2,
                                                 nullptr, (float4*)out, N);
    cudaStreamWaitEvent(s0, g_evT1, 0);
    k_add<<<(N * 32 + 255) / 256, 256, 0, s0>>>((float4*)out, (const float4*)T1, N * 32);
}

// round 11
// speedup vs baseline: 4.0959x; 1.3152x over previous
#include <cuda_runtime.h>
#include <cuda_fp16.h>
#include <cstdint>

// Problem constants (fixed by the reference)
constexpr long long Nn = 50000;
constexpr long long Ee = 800000;
constexpr long long RP = 50008;   // rowptr stride (>= Nn+1, multiple of 4)

// Scratch layout inside one __device__ array (units of float = 4B; all offsets
// multiples of 4 -> 16B aligned).
constexpr long long OFF_DINV1 = 0;
constexpr long long OFF_DINV2 = OFF_DINV1 + Nn;
constexpr long long OFF_CNT1  = OFF_DINV2 + Nn;            // int
constexpr long long OFF_CNT2  = OFF_CNT1  + Nn;            // int
constexpr long long OFF_RP1   = OFF_CNT2  + Nn;            // int rowptr
constexpr long long OFF_RP2   = OFF_RP1   + RP;
constexpr long long OFF_FP1   = OFF_RP2   + RP;            // int fill cursor
constexpr long long OFF_FP2   = OFF_FP1   + Nn;
constexpr long long OFF_IDX1  = OFF_FP2   + Nn;            // src1,dst1 [2E] int
constexpr long long OFF_IDX2  = OFF_IDX1  + 2 * Ee;        // src2,dst2 [2E] int
constexpr long long OFF_ADJ1  = OFF_IDX2  + 2 * Ee;        // CSR adj   [E] int
constexpr long long OFF_ADJ2  = OFF_ADJ1  + Ee;
constexpr long long OFF_XS1   = OFF_ADJ2  + Ee;            // x*dinv1 half [N,128]
constexpr long long OFF_XS2   = OFF_XS1   + Nn * 64;
constexpr long long OFF_XA1   = OFF_XS2   + Nn * 64;       // agg(x) half  [N,128]
constexpr long long OFF_XA2   = OFF_XA1   + Nn * 64;
constexpr long long OFF_H1    = OFF_XA2   + Nn * 64;       // relu half    [N,256]
constexpr long long OFF_H2    = OFF_H1    + Nn * 128;
constexpr long long OFF_GS1   = OFF_H2    + Nn * 128;      // g*dinv half  [N,128]
constexpr long long OFF_GS2   = OFF_GS1   + Nn * 64;
constexpr long long OFF_T1    = OFF_GS2   + Nn * 64;       // graph1 term fp32 [N,128]
constexpr long long OFF_WH0   = OFF_T1    + Nn * 128;      // W0^T half [256][128]
constexpr long long OFF_WH1   = OFF_WH0   + 16384;
constexpr long long OFF_WH2   = OFF_WH1   + 16384;         // W2^T half [128][256]
constexpr long long OFF_WH3   = OFF_WH2   + 16384;
constexpr long long SCRATCH   = OFF_WH3   + 16384;

__device__ float g_scratch[SCRATCH];
// 1 if edge indices are int64, 0 if int32. Statically 1; k_detect_zero clears
// it iff the data is int32. Deterministic for fixed input (int64 input never
// writes; int32 input always converges to 0 on the first call and stays 0).
__device__ int g_is64 = 1;

// ---------------------------------------------------------------------------
// detect (sampled) + zero degree counters
// ---------------------------------------------------------------------------
__global__ void k_detect_zero(const long long* __restrict__ p, int words, int n,
                              int* __restrict__ cnt, int nzero) {
    int i = blockIdx.x * blockDim.x + threadIdx.x;
    if (i < nzero) cnt[i] = 0;
    if (i < words) {
        long long v = p[i];
        if (v < 0 || v >= n) g_is64 = 0;   // benign race: all writers write 0
    }
}

// decode both graphs' indices + degree histogram (dst halves) in one pass
__global__ void k_convert_deg(const void* __restrict__ p1, const void* __restrict__ p2,
                              int* __restrict__ o1, int* __restrict__ o2,
                              int E2, int E, int* __restrict__ cnt1, int* __restrict__ cnt2) {
    int i = blockIdx.x * blockDim.x + threadIdx.x;
    if (i < E2) {
        int v1, v2;
        if (g_is64) {
            v1 = (int)((const long long*)p1)[i];
            v2 = (int)((const long long*)p2)[i];
        } else {
            v1 = ((const int*)p1)[i];
            v2 = ((const int*)p2)[i];
        }
        o1[i] = v1;
        o2[i] = v2;
        if (i >= E) {                       // dst halves
            atomicAdd(&cnt1[v1], 1);
            atomicAdd(&cnt2[v2], 1);
        }
    }
}

// exclusive scan of one graph's counts (single block) + dinv compute
__global__ void k_scan1(const int* __restrict__ cnt, int* __restrict__ rp,
                        int* __restrict__ fp, float* __restrict__ dinv, int n) {
    __shared__ int wsum[32];
    __shared__ int s_base;
    const int t = threadIdx.x;
    const int lane = t & 31, wid = t >> 5;
    if (t == 0) s_base = 0;
    __syncthreads();
    for (int chunk = 0; chunk < n; chunk += 1024) {
        int v = (chunk + t < n) ? cnt[chunk + t] : 0;
        if (chunk + t < n) dinv[chunk + t] = rsqrtf((float)v + 1.0f);
        int incl = v;
#pragma unroll
        for (int off = 1; off < 32; off <<= 1) {
            int x = __shfl_up_sync(0xffffffffu, incl, off);
            if (lane >= off) incl += x;
        }
        if (lane == 31) wsum[wid] = incl;
        __syncthreads();
        if (wid == 0) {
            int s = wsum[lane];
#pragma unroll
            for (int off = 1; off < 32; off <<= 1) {
                int x = __shfl_up_sync(0xffffffffu, s, off);
                if (lane >= off) s += x;
            }
            wsum[lane] = s;
        }
        __syncthreads();
        int warpoff = (wid == 0) ? 0 : wsum[wid - 1];
        int base = s_base;
        __syncthreads();
        if (chunk + t < n) {
            int ex = base + warpoff + incl - v;
            rp[chunk + t] = ex;
            fp[chunk + t] = ex;
        }
        if (t == 0) s_base = base + wsum[31];
        __syncthreads();
    }
    if (t == 0) rp[n] = s_base;
}

__global__ void k_fill1(const int* __restrict__ src, const int* __restrict__ dst,
                        int* __restrict__ fp, int* __restrict__ adj, int E) {
    int e = blockIdx.x * blockDim.x + threadIdx.x;
    if (e < E) {
        int p = atomicAdd(&fp[dst[e]], 1);
        adj[p] = src[e];
    }
}

// prescale to half: Xs[i] = x[i] * dinv[row], packed half2x2 per float4
__global__ void k_prescale_h(const float4* __restrict__ x, const float* __restrict__ dinv,
                             uint2* __restrict__ Xs, int total4) {
    int i = blockIdx.x * blockDim.x + threadIdx.x;
    if (i < total4) {
        int row = i >> 5;
        float4 v = x[i];
        float d = dinv[row];
        uint2 o;
        *(__half2*)&o.x = __floats2half2_rn(v.x * d, v.y * d);
        *(__half2*)&o.y = __floats2half2_rn(v.z * d, v.w * d);
        Xs[i] = o;
    }
}

// weight prep: Wh[n*K + k] = half(W[k*N + n])  (transpose + halve, all 4)
__global__ void k_prep_w(const float* __restrict__ W0, const float* __restrict__ W1,
                         const float* __restrict__ W2, const float* __restrict__ W3,
                         __half* __restrict__ Wh0, __half* __restrict__ Wh1,
                         __half* __restrict__ Wh2, __half* __restrict__ Wh3) {
    int id = blockIdx.x * 256 + threadIdx.x;       // 0..131071
    int seg = id >> 15;
    int local = id & 32767;
    const float* W;
    __half* Wh;
    int K, Nc;
    if (seg == 0)      { W = W0; Wh = Wh0; K = 128; Nc = 256; }
    else if (seg == 1) { W = W1; Wh = Wh1; K = 128; Nc = 256; }
    else if (seg == 2) { W = W2; Wh = Wh2; K = 256; Nc = 128; }
    else               { W = W3; Wh = Wh3; K = 256; Nc = 128; }
    int k = local / Nc, n = local % Nc;            // coalesced read
    Wh[n * K + k] = __float2half_rn(W[local]);
}

// out += T (float4)
__global__ void k_add(float4* __restrict__ out, const float4* __restrict__ t, int n4) {
    int i = blockIdx.x * blockDim.x + threadIdx.x;
    if (i < n4) {
        float4 o = out[i];
        float4 v = t[i];
        o.x += v.x; o.y += v.y; o.z += v.z; o.w += v.w;
        out[i] = o;
    }
}

// ---------------------------------------------------------------------------
// gathers (half2 payload, fp32 accumulate). One warp per node, 4 cols/thread.
// ---------------------------------------------------------------------------
// Xa[node] = half( x[node]*dinv^2 + dinv * sum Xs[adj] )
__global__ __launch_bounds__(256) void k_gather_xa(const int* __restrict__ rowptr,
                                                   const int* __restrict__ adj,
                                                   const float* __restrict__ dinv,
                                                   const uint2* __restrict__ Xs,
                                                   const float4* __restrict__ xself,
                                                   uint2* __restrict__ Xa, int N) {
    int node = blockIdx.x * 8 + (threadIdx.x >> 5);
    int c = threadIdx.x & 31;
    if (node >= N) return;
    int beg = rowptr[node], end = rowptr[node + 1];
    float s0 = 0.f, s1 = 0.f, s2 = 0.f, s3 = 0.f;
    int j = beg;
    for (; j + 2 <= end; j += 2) {
        uint2 h0 = Xs[(long long)adj[j] * 32 + c];
        uint2 h1 = Xs[(long long)adj[j + 1] * 32 + c];
        float2 a0 = __half22float2(*(__half2*)&h0.x), a1 = __half22float2(*(__half2*)&h0.y);
        float2 b0 = __half22float2(*(__half2*)&h1.x), b1 = __half22float2(*(__half2*)&h1.y);
        s0 += a0.x + b0.x; s1 += a0.y + b0.y;
        s2 += a1.x + b1.x; s3 += a1.y + b1.y;
    }
    if (j < end) {
        uint2 h0 = Xs[(long long)adj[j] * 32 + c];
        float2 a0 = __half22float2(*(__half2*)&h0.x), a1 = __half22float2(*(__half2*)&h0.y);
        s0 += a0.x; s1 += a0.y; s2 += a1.x; s3 += a1.y;
    }
    float w = dinv[node], w2 = w * w;
    float4 sv = xself[(long long)node * 32 + c];
    uint2 o;
    *(__half2*)&o.x = __floats2half2_rn(sv.x * w2 + s0 * w, sv.y * w2 + s1 * w);
    *(__half2*)&o.y = __floats2half2_rn(sv.z * w2 + s2 * w, sv.w * w2 + s3 * w);
    Xa[(long long)node * 32 + c] = o;
}

// GM=1: Out[node] += dinv * sum Gs[adj]   (fp32 out)
// GM=2: Out[node]  = dinv * sum Gs[adj]   (fp32 T1)
template <int GM>
__global__ __launch_bounds__(256) void k_gather_out(const int* __restrict__ rowptr,
                                                    const int* __restrict__ adj,
                                                    const float* __restrict__ dinv,
                                                    const uint2* __restrict__ Gs,
                                                    float4* __restrict__ Out, int N) {
    int node = blockIdx.x * 8 + (threadIdx.x >> 5);
    int c = threadIdx.x & 31;
    if (node >= N) return;
    int beg = rowptr[node], end = rowptr[node + 1];
    float s0 = 0.f, s1 = 0.f, s2 = 0.f, s3 = 0.f;
    int j = beg;
    for (; j + 2 <= end; j += 2) {
        uint2 h0 = Gs[(long long)adj[j] * 32 + c];
        uint2 h1 = Gs[(long long)adj[j + 1] * 32 + c];
        float2 a0 = __half22float2(*(__half2*)&h0.x), a1 = __half22float2(*(__half2*)&h0.y);
        float2 b0 = __half22float2(*(__half2*)&h1.x), b1 = __half22float2(*(__half2*)&h1.y);
        s0 += a0.x + b0.x; s1 += a0.y + b0.y;
        s2 += a1.x + b1.x; s3 += a1.y + b1.y;
    }
    if (j < end) {
        uint2 h0 = Gs[(long long)adj[j] * 32 + c];
        float2 a0 = __half22float2(*(__half2*)&h0.x), a1 = __half22float2(*(__half2*)&h0.y);
        s0 += a0.x; s1 += a0.y; s2 += a1.x; s3 += a1.y;
    }
    float w = dinv[node];
    long long p = (long long)node * 32 + c;
    float4 a = (GM == 1) ? Out[p] : make_float4(0.f, 0.f, 0.f, 0.f);
    a.x += s0 * w; a.y += s1 * w; a.z += s2 * w; a.w += s3 * w;
    Out[p] = a;
}

// ---------------------------------------------------------------------------
// fp16 tensor-core GEMM (m16n8k16, fp32 accum) with cp.async double buffering.
//   C = A[M,KT] * Wh^T  where Wh is [Ncol][KT] half (pre-transposed weights).
//   BM=128, BN=64, BK=32; 256 threads = 8 warps (4 M x 2 N), warp tile 32x32.
//   SMEM: pad-40 half rows -> all fragment LDS conflict-free.
// MODE 0: OutH = half(relu(acc + bias2[c]))                       (layer 1)
// MODE 1: OutS = half(acc*dv) ; OutF  = acc*dv^2 + bias2 + bias3  (layer 2a)
// MODE 2: OutS = half(acc*dv) ; OutF += acc*dv^2                  (layer 2b)
// ---------------------------------------------------------------------------
__device__ __forceinline__ void mma_f16(float* c, uint32_t a0, uint32_t a1,
                                        uint32_t a2, uint32_t a3,
                                        uint32_t b0, uint32_t b1) {
    asm volatile(
        "mma.sync.aligned.m16n8k16.row.col.f32.f16.f16.f32 "
        "{%0,%1,%2,%3}, {%4,%5,%6,%7}, {%8,%9}, {%0,%1,%2,%3};\n"
        : "+f"(c[0]), "+f"(c[1]), "+f"(c[2]), "+f"(c[3])
        : "r"(a0), "r"(a1), "r"(a2), "r"(a3), "r"(b0), "r"(b1));
}

__device__ __forceinline__ uint32_t smem_u32(const void* p) {
    return (uint32_t)__cvta_generic_to_shared(p);
}
__device__ __forceinline__ void cp16(uint32_t dst, const void* src, int sz) {
    asm volatile("cp.async.cg.shared.global [%0], [%1], 16, %2;\n"
                 :: "r"(dst), "l"(src), "r"(sz));
}
__device__ __forceinline__ void cp_commit() {
    asm volatile("cp.async.commit_group;\n");
}
template <int N_> __device__ __forceinline__ void cp_wait() {
    asm volatile("cp.async.wait_group %0;\n" :: "n"(N_));
}

template <int MODE, int KT>
__global__ __launch_bounds__(256) void k_gemm_h(const __half* __restrict__ A,
                                                const __half* __restrict__ B,   // Wh [Ncol][KT]
                                                const float* __restrict__ dinv,
                                                __half* __restrict__ OutS,      // Gs half
                                                __half* __restrict__ OutH,      // H half
                                                float* __restrict__ OutF,       // out fp32
                                                const float* __restrict__ bias2,
                                                const float* __restrict__ bias3,
                                                int M, int Ncol) {
    __shared__ __half As[2][128 * 40];   // pad 40 halves/row
    __shared__ __half Bs[2][64 * 40];

    const int tid  = threadIdx.x;
    const int wid  = tid >> 5;
    const int lane = tid & 31;
    const int gid  = lane >> 2;     // 0..7
    const int tig  = lane & 3;      // 0..3
    const int wm   = wid >> 1;      // 0..3
    const int wn   = wid & 1;       // 0..1
    const int rowBase = blockIdx.y * 128;
    const int colBase = blockIdx.x * 64;
    constexpr int NK = KT / 32;

    auto loadTiles = [&](int i) {
        int k0 = i * 32;
        int buf = i & 1;
        // A: 128 rows x 32 half = 512 x 16B chunks, 2 per thread
#pragma unroll
        for (int t = 0; t < 2; t++) {
            int idx = tid + t * 256;        // 0..511
            int r   = idx >> 2;
            int ch  = idx & 3;
            int row = rowBase + r;
            const __half* g = A + (long long)(row < M ? row : 0) * KT + k0 + ch * 8;
            cp16(smem_u32(&As[buf][r * 40 + ch * 8]), g, row < M ? 16 : 0);
        }
        // B: 64 n-rows x 32 half = 256 chunks, 1 per thread
        {
            int n  = tid >> 2;
            int ch = tid & 3;
            const __half* g = B + (long long)(colBase + n) * KT + k0 + ch * 8;
            cp16(smem_u32(&Bs[buf][n * 40 + ch * 8]), g, 16);
        }
        cp_commit();
    };

    float acc[2][4][4] = {};
    loadTiles(0);

#pragma unroll
    for (int i = 0; i < NK; i++) {
        if (i + 1 < NK) loadTiles(i + 1);
        if (i + 1 < NK) cp_wait<1>(); else cp_wait<0>();
        __syncthreads();

        const __half* as = As[i & 1];
        const __half* bs = Bs[i & 1];
#pragma unroll
        for (int ks = 0; ks < 32; ks += 16) {
            uint32_t a[2][4];
#pragma unroll
            for (int mt = 0; mt < 2; mt++) {
                int r = wm * 32 + mt * 16 + gid;
                const uint32_t* p0 = (const uint32_t*)(as + r * 40 + ks + 2 * tig);
                const uint32_t* p1 = (const uint32_t*)(as + (r + 8) * 40 + ks + 2 * tig);
                a[mt][0] = p0[0];
                a[mt][1] = p1[0];
                a[mt][2] = p0[4];
                a[mt][3] = p1[4];
            }
            uint32_t b[4][2];
#pragma unroll
            for (int nt = 0; nt < 4; nt++) {
                int n = wn * 32 + nt * 8 + gid;
                const uint32_t* p = (const uint32_t*)(bs + n * 40 + ks + 2 * tig);
                b[nt][0] = p[0];
                b[nt][1] = p[4];
            }
#pragma unroll
            for (int mt = 0; mt < 2; mt++)
#pragma unroll
                for (int nt = 0; nt < 4; nt++)
                    mma_f16(acc[mt][nt], a[mt][0], a[mt][1], a[mt][2], a[mt][3],
                            b[nt][0], b[nt][1]);
        }
        __syncthreads();
    }

    // epilogue: c0,c1 -> row gid (cols 2tig,2tig+1); c2,c3 -> row gid+8
#pragma unroll
    for (int mt = 0; mt < 2; mt++) {
#pragma unroll
        for (int h = 0; h < 2; h++) {
            int row = rowBase + wm * 32 + mt * 16 + gid + h * 8;
            if (row >= M) continue;
            float dv  = (MODE == 0) ? 0.f : dinv[row];
            float dv2 = dv * dv;
            long long rb = (long long)row * Ncol;
#pragma unroll
            for (int nt = 0; nt < 4; nt++) {
                int c = colBase + wn * 32 + nt * 8 + 2 * tig;
                float v0 = acc[mt][nt][2 * h + 0];
                float v1 = acc[mt][nt][2 * h + 1];
                if (MODE == 0) {
                    float2 bb = *(const float2*)(bias2 + c);
                    *(__half2*)(OutH + rb + c) =
                        __floats2half2_rn(fmaxf(v0 + bb.x, 0.f), fmaxf(v1 + bb.y, 0.f));
                } else if (MODE == 1) {
                    *(__half2*)(OutS + rb + c) = __floats2half2_rn(v0 * dv, v1 * dv);
                    float2 p2 = *(const float2*)(bias2 + c);
                    float2 p3 = *(const float2*)(bias3 + c);
                    *(float2*)(OutF + rb + c) =
                        make_float2(v0 * dv2 + p2.x + p3.x, v1 * dv2 + p2.y + p3.y);
                } else {
                    *(__half2*)(OutS + rb + c) = __floats2half2_rn(v0 * dv, v1 * dv);
                    float2 o = *(const float2*)(OutF + rb + c);
                    o.x += v0 * dv2;
                    o.y += v1 * dv2;
                    *(float2*)(OutF + rb + c) = o;
                }
            }
        }
    }
}

// ---------------------------------------------------------------------------
// host side: two-stream overlapped schedule (graph-capture-legal fork/join).
// IMPORTANT: s2's FIRST operation must be a wait on an event recorded in the
// capturing stream s0 — that is how a side stream joins the capture.
// ---------------------------------------------------------------------------
static cudaStream_t g_s2   = nullptr;
static cudaEvent_t  g_evF  = nullptr;   // fork point (s0, first)
static cudaEvent_t  g_evW  = nullptr;   // weights prepped (s2)
static cudaEvent_t  g_evC  = nullptr;   // after convert+deg (s0)
static cudaEvent_t  g_evX1 = nullptr;   // after gather Xa1 (stagger gate, s0)
static cudaEvent_t  g_evH2 = nullptr;   // after GEMM H2 (s2)
static cudaEvent_t  g_evM1 = nullptr;   // after GEMM MODE1 (s0)
static cudaEvent_t  g_evT1 = nullptr;   // after gather T1 (s2, join point)

extern "C" void kernel_launch(void* const* d_in, const int* in_sizes, int n_in,
                              void* d_out, int out_size) {
    if (!g_s2) {
        cudaStreamCreateWithFlags(&g_s2, cudaStreamNonBlocking);
        cudaEventCreateWithFlags(&g_evF,  cudaEventDisableTiming);
        cudaEventCreateWithFlags(&g_evW,  cudaEventDisableTiming);
        cudaEventCreateWithFlags(&g_evC,  cudaEventDisableTiming);
        cudaEventCreateWithFlags(&g_evX1, cudaEventDisableTiming);
        cudaEventCreateWithFlags(&g_evH2, cudaEventDisableTiming);
        cudaEventCreateWithFlags(&g_evM1, cudaEventDisableTiming);
        cudaEventCreateWithFlags(&g_evT1, cudaEventDisableTiming);
    }

    const float* x   = (const float*)d_in[0];
    const void*  ei  = d_in[1];
    const void*  ei2 = d_in[2];
    const float* W0 = (const float*)d_in[3];
    const float* b0 = (const float*)d_in[4];
    const float* W1 = (const float*)d_in[5];
    const float* b1 = (const float*)d_in[6];
    const float* W2 = (const float*)d_in[7];
    const float* b2 = (const float*)d_in[8];
    const float* W3 = (const float*)d_in[9];
    const float* b3 = (const float*)d_in[10];

    const int N = in_sizes[0] / 128;   // 50000
    const int E = in_sizes[1] / 2;     // 800000

    float* S = nullptr;
    cudaGetSymbolAddress((void**)&S, g_scratch);
    float*  dinv1 = S + OFF_DINV1;
    float*  dinv2 = S + OFF_DINV2;
    int*    cnt1  = (int*)(S + OFF_CNT1);
    int*    cnt2  = (int*)(S + OFF_CNT2);
    int*    rp1   = (int*)(S + OFF_RP1);
    int*    rp2   = (int*)(S + OFF_RP2);
    int*    fp1   = (int*)(S + OFF_FP1);
    int*    fp2   = (int*)(S + OFF_FP2);
    int*    idx1  = (int*)(S + OFF_IDX1);
    int*    idx2  = (int*)(S + OFF_IDX2);
    int*    adj1  = (int*)(S + OFF_ADJ1);
    int*    adj2  = (int*)(S + OFF_ADJ2);
    __half* Xs1   = (__half*)(S + OFF_XS1);
    __half* Xs2   = (__half*)(S + OFF_XS2);
    __half* Xa1   = (__half*)(S + OFF_XA1);
    __half* Xa2   = (__half*)(S + OFF_XA2);
    __half* H1    = (__half*)(S + OFF_H1);
    __half* H2    = (__half*)(S + OFF_H2);
    __half* Gs1   = (__half*)(S + OFF_GS1);
    __half* Gs2   = (__half*)(S + OFF_GS2);
    float*  T1    = S + OFF_T1;
    __half* Wh0   = (__half*)(S + OFF_WH0);
    __half* Wh1   = (__half*)(S + OFF_WH1);
    __half* Wh2   = (__half*)(S + OFF_WH2);
    __half* Wh3   = (__half*)(S + OFF_WH3);
    float*  out   = (float*)d_out;

    cudaStream_t s0 = 0;
    cudaStream_t s2 = g_s2;

    const int* src1 = idx1;
    const int* dst1 = idx1 + E;
    const int* src2 = idx2;
    const int* dst2 = idx2 + E;

    // ---- s0: first kernel (dtype probe + zero counters), then FORK
    {
        int words = (E < 65536) ? E : 65536;
        int span  = (2 * N > words) ? 2 * N : words;
        k_detect_zero<<<(span + 255) / 256, 256, 0, s0>>>((const long long*)ei, words, N, cnt1, 2 * N);
    }
    cudaEventRecord(g_evF, s0);

    // ---- s2 joins capture via wait(evF), then weight prep (concurrent w/ decode)
    cudaStreamWaitEvent(s2, g_evF, 0);
    k_prep_w<<<512, 256, 0, s2>>>(W0, W1, W2, W3, Wh0, Wh1, Wh2, Wh3);
    cudaEventRecord(g_evW, s2);

    // ---- s0: decode + degree histogram
    k_convert_deg<<<(2 * E + 255) / 256, 256, 0, s0>>>(ei, ei2, idx1, idx2, 2 * E, E, cnt1, cnt2);
    cudaEventRecord(g_evC, s0);

    // ---- graph-1 chain on s0
    k_scan1<<<1, 1024, 0, s0>>>(cnt1, rp1, fp1, dinv1, N);
    k_fill1<<<(E + 255) / 256, 256, 0, s0>>>(src1, dst1, fp1, adj1, E);
    k_prescale_h<<<(N * 32 + 255) / 256, 256, 0, s0>>>((const float4*)x, dinv1, (uint2*)Xs1, N * 32);
    k_gather_xa<<<(N + 7) / 8, 256, 0, s0>>>(rp1, adj1, dinv1, (const uint2*)Xs1,
                                             (const float4*)x, (uint2*)Xa1, N);
    cudaEventRecord(g_evX1, s0);

    // ---- graph-2 chain on s2 (gather staggered after Xa1)
    cudaStreamWaitEvent(s2, g_evC, 0);
    k_scan1<<<1, 1024, 0, s2>>>(cnt2, rp2, fp2, dinv2, N);
    k_fill1<<<(E + 255) / 256, 256, 0, s2>>>(src2, dst2, fp2, adj2, E);
    k_prescale_h<<<(N * 32 + 255) / 256, 256, 0, s2>>>((const float4*)x, dinv2, (uint2*)Xs2, N * 32);
    cudaStreamWaitEvent(s2, g_evX1, 0);
    k_gather_xa<<<(N + 7) / 8, 256, 0, s2>>>(rp2, adj2, dinv2, (const uint2*)Xs2,
                                             (const float4*)x, (uint2*)Xa2, N);

    // ---- layer-1 GEMMs: H = relu(Xa @ W + b)   (KT=128, Ncol=256)
    dim3 g1(4, (N + 127) / 128);
    cudaStreamWaitEvent(s0, g_evW, 0);
    k_gemm_h<0, 128><<<g1, 256, 0, s0>>>(Xa1, Wh0, nullptr, nullptr, H1, nullptr, b0, nullptr, N, 256);
    k_gemm_h<0, 128><<<g1, 256, 0, s2>>>(Xa2, Wh1, nullptr, nullptr, H2, nullptr, b1, nullptr, N, 256);
    cudaEventRecord(g_evH2, s2);

    // ---- layer-2 GEMMs (KT=256, Ncol=128)
    dim3 g2(2, (N + 127) / 128);
    k_gemm_h<1, 256><<<g2, 256, 0, s0>>>(H1, Wh2, dinv1, Gs1, nullptr, out, b2, b3, N, 128);
    cudaEventRecord(g_evM1, s0);

    // graph-1 output gather into T1 on s2, hidden under MODE2
    cudaStreamWaitEvent(s2, g_evM1, 0);
    k_gather_out<2><<<(N + 7) / 8, 256, 0, s2>>>(rp1, adj1, dinv1, (const uint2*)Gs1,
                                                 (float4*)T1, N);
    cudaEventRecord(g_evT1, s2);

    cudaStreamWaitEvent(s0, g_evH2, 0);
    k_gemm_h<2, 256><<<g2, 256, 0, s0>>>(H2, Wh3, dinv2, Gs2, nullptr, out, nullptr, nullptr, N, 128);

    // ---- graph-2 output gather accumulates into out, then add T1 (join)
    k_gather_out<1><<<(N + 7) / 8, 256, 0, s0>>>(rp2, adj2, dinv2, (const uint2*)Gs2,
                                                 (float4*)out, N);
    cudaStreamWaitEvent(s0, g_evT1, 0);
    k_add<<<(N * 32 + 255) / 256, 256, 0, s0>>>((float4*)out, (const float4*)T1, N * 32);
}

// round 13
// speedup vs baseline: 4.8044x; 1.1730x over previous
#include <cuda_runtime.h>
#include <cuda_fp16.h>
#include <cstdint>

// Problem constants (fixed by the reference)
constexpr long long Nn = 50000;
constexpr long long Ee = 800000;
constexpr long long RP = 50008;   // rowptr stride (>= Nn+1, multiple of 4)
constexpr int SCAN_NB = (int)((Nn + 1023) / 1024);   // 49 scan blocks

// Scratch layout inside one __device__ array (units of float = 4B; all offsets
// multiples of 4 -> 16B aligned).
constexpr long long OFF_DINV1 = 0;
constexpr long long OFF_DINV2 = OFF_DINV1 + Nn;
constexpr long long OFF_CNT1  = OFF_DINV2 + Nn;            // int
constexpr long long OFF_CNT2  = OFF_CNT1  + Nn;            // int
constexpr long long OFF_RP1   = OFF_CNT2  + Nn;            // int rowptr
constexpr long long OFF_RP2   = OFF_RP1   + RP;
constexpr long long OFF_FP1   = OFF_RP2   + RP;            // int fill cursor
constexpr long long OFF_FP2   = OFF_FP1   + Nn;
constexpr long long OFF_BS1   = OFF_FP2   + Nn;            // int block sums [64]
constexpr long long OFF_BS2   = OFF_BS1   + 64;
constexpr long long OFF_IDX1  = OFF_BS2   + 64;            // src1,dst1 [2E] int
constexpr long long OFF_IDX2  = OFF_IDX1  + 2 * Ee;        // src2,dst2 [2E] int
constexpr long long OFF_ADJ1  = OFF_IDX2  + 2 * Ee;        // CSR adj   [E] int
constexpr long long OFF_ADJ2  = OFF_ADJ1  + Ee;
constexpr long long OFF_XS1   = OFF_ADJ2  + Ee;            // x*dinv1 half [N,128]
constexpr long long OFF_XS2   = OFF_XS1   + Nn * 64;
constexpr long long OFF_XA1   = OFF_XS2   + Nn * 64;       // agg(x) half  [N,128]
constexpr long long OFF_XA2   = OFF_XA1   + Nn * 64;
constexpr long long OFF_H1    = OFF_XA2   + Nn * 64;       // relu half    [N,256]
constexpr long long OFF_H2    = OFF_H1    + Nn * 128;
constexpr long long OFF_GS1   = OFF_H2    + Nn * 128;      // g*dinv half  [N,128]
constexpr long long OFF_GS2   = OFF_GS1   + Nn * 64;
constexpr long long OFF_T1    = OFF_GS2   + Nn * 64;       // graph1 term fp32 [N,128]
constexpr long long OFF_WH0   = OFF_T1    + Nn * 128;      // W0^T half [256][128]
constexpr long long OFF_WH1   = OFF_WH0   + 16384;
constexpr long long OFF_WH2   = OFF_WH1   + 16384;         // W2^T half [128][256]
constexpr long long OFF_WH3   = OFF_WH2   + 16384;
constexpr long long SCRATCH   = OFF_WH3   + 16384;

__device__ float g_scratch[SCRATCH];
// 1 if edge indices are int64, 0 if int32. Statically 1; k_detect_zero clears
// it iff the data is int32. Deterministic for fixed input.
__device__ int g_is64 = 1;

// ---------------------------------------------------------------------------
// detect (sampled) + zero degree counters
// ---------------------------------------------------------------------------
__global__ void k_detect_zero(const long long* __restrict__ p, int words, int n,
                              int* __restrict__ cnt, int nzero) {
    int i = blockIdx.x * blockDim.x + threadIdx.x;
    if (i < nzero) cnt[i] = 0;
    if (i < words) {
        long long v = p[i];
        if (v < 0 || v >= n) g_is64 = 0;   // benign race: all writers write 0
    }
}

// decode both graphs' indices + degree histogram (dst halves) in one pass
__global__ void k_convert_deg(const void* __restrict__ p1, const void* __restrict__ p2,
                              int* __restrict__ o1, int* __restrict__ o2,
                              int E2, int E, int* __restrict__ cnt1, int* __restrict__ cnt2) {
    int i = blockIdx.x * blockDim.x + threadIdx.x;
    if (i < E2) {
        int v1, v2;
        if (g_is64) {
            v1 = (int)((const long long*)p1)[i];
            v2 = (int)((const long long*)p2)[i];
        } else {
            v1 = ((const int*)p1)[i];
            v2 = ((const int*)p2)[i];
        }
        o1[i] = v1;
        o2[i] = v2;
        if (i >= E) {                       // dst halves
            atomicAdd(&cnt1[v1], 1);
            atomicAdd(&cnt2[v2], 1);
        }
    }
}

// ---------------------------------------------------------------------------
// multi-block exclusive scan (3 phases) + dinv compute
// ---------------------------------------------------------------------------
// phase A: per-block (1024 elems) local exclusive scan into rp; block total to
// bsum; dinv computed on the fly.
__global__ __launch_bounds__(1024) void k_scan_a(const int* __restrict__ cnt,
                                                 int* __restrict__ rp,
                                                 float* __restrict__ dinv,
                                                 int* __restrict__ bsum, int n) {
    __shared__ int wsum[32];
    const int t = threadIdx.x;
    const int lane = t & 31, wid = t >> 5;
    int i = blockIdx.x * 1024 + t;
    int v = (i < n) ? cnt[i] : 0;
    if (i < n) dinv[i] = rsqrtf((float)v + 1.0f);
    int incl = v;
#pragma unroll
    for (int off = 1; off < 32; off <<= 1) {
        int x = __shfl_up_sync(0xffffffffu, incl, off);
        if (lane >= off) incl += x;
    }
    if (lane == 31) wsum[wid] = incl;
    __syncthreads();
    if (wid == 0) {
        int s = wsum[lane];
#pragma unroll
        for (int off = 1; off < 32; off <<= 1) {
            int x = __shfl_up_sync(0xffffffffu, s, off);
            if (lane >= off) s += x;
        }
        wsum[lane] = s;
    }
    __syncthreads();
    int warpoff = (wid == 0) ? 0 : wsum[wid - 1];
    if (i < n) rp[i] = warpoff + incl - v;
    if (t == 0) bsum[blockIdx.x] = wsum[31];
}

// phase B: single small block scans block totals (nb <= 64); writes rp[n].
__global__ void k_scan_b(int* __restrict__ bsum, int nb, int* __restrict__ rp, int n) {
    __shared__ int s[64];
    int t = threadIdx.x;
    int v = (t < nb) ? bsum[t] : 0;
    s[t] = v;
    __syncthreads();
#pragma unroll
    for (int off = 1; off < 64; off <<= 1) {
        int x = (t >= off) ? s[t - off] : 0;
        __syncthreads();
        s[t] += x;
        __syncthreads();
    }
    if (t < nb) bsum[t] = s[t] - v;        // exclusive
    if (t == nb - 1) rp[n] = s[t];         // grand total
}

// phase C: add block offsets; mirror into fill cursor.
__global__ __launch_bounds__(1024) void k_scan_c(int* __restrict__ rp, int* __restrict__ fp,
                                                 const int* __restrict__ bsum, int n) {
    int i = blockIdx.x * 1024 + threadIdx.x;
    if (i < n) {
        int v = rp[i] + bsum[blockIdx.x];
        rp[i] = v;
        fp[i] = v;
    }
}

__global__ void k_fill1(const int* __restrict__ src, const int* __restrict__ dst,
                        int* __restrict__ fp, int* __restrict__ adj, int E) {
    int e = blockIdx.x * blockDim.x + threadIdx.x;
    if (e < E) {
        int p = atomicAdd(&fp[dst[e]], 1);
        adj[p] = src[e];
    }
}

// prescale to half: Xs[i] = x[i] * dinv[row], packed half2x2 per float4
__global__ void k_prescale_h(const float4* __restrict__ x, const float* __restrict__ dinv,
                             uint2* __restrict__ Xs, int total4) {
    int i = blockIdx.x * blockDim.x + threadIdx.x;
    if (i < total4) {
        int row = i >> 5;
        float4 v = x[i];
        float d = dinv[row];
        uint2 o;
        *(__half2*)&o.x = __floats2half2_rn(v.x * d, v.y * d);
        *(__half2*)&o.y = __floats2half2_rn(v.z * d, v.w * d);
        Xs[i] = o;
    }
}

// weight prep: Wh[n*K + k] = half(W[k*N + n])  (transpose + halve, all 4)
__global__ void k_prep_w(const float* __restrict__ W0, const float* __restrict__ W1,
                         const float* __restrict__ W2, const float* __restrict__ W3,
                         __half* __restrict__ Wh0, __half* __restrict__ Wh1,
                         __half* __restrict__ Wh2, __half* __restrict__ Wh3) {
    int id = blockIdx.x * 256 + threadIdx.x;       // 0..131071
    int seg = id >> 15;
    int local = id & 32767;
    const float* W;
    __half* Wh;
    int K, Nc;
    if (seg == 0)      { W = W0; Wh = Wh0; K = 128; Nc = 256; }
    else if (seg == 1) { W = W1; Wh = Wh1; K = 128; Nc = 256; }
    else if (seg == 2) { W = W2; Wh = Wh2; K = 256; Nc = 128; }
    else               { W = W3; Wh = Wh3; K = 256; Nc = 128; }
    int k = local / Nc, n = local % Nc;            // coalesced read
    Wh[n * K + k] = __float2half_rn(W[local]);
}

// ---------------------------------------------------------------------------
// gathers (half2 payload, fp32 accumulate). One warp per node, 4 cols/thread.
// ---------------------------------------------------------------------------
// Xa[node] = half( x[node]*dinv^2 + dinv * sum Xs[adj] )
__global__ __launch_bounds__(256) void k_gather_xa(const int* __restrict__ rowptr,
                                                   const int* __restrict__ adj,
                                                   const float* __restrict__ dinv,
                                                   const uint2* __restrict__ Xs,
                                                   const float4* __restrict__ xself,
                                                   uint2* __restrict__ Xa, int N) {
    int node = blockIdx.x * 8 + (threadIdx.x >> 5);
    int c = threadIdx.x & 31;
    if (node >= N) return;
    int beg = rowptr[node], end = rowptr[node + 1];
    float s0 = 0.f, s1 = 0.f, s2 = 0.f, s3 = 0.f;
    int j = beg;
    for (; j + 2 <= end; j += 2) {
        uint2 h0 = Xs[(long long)adj[j] * 32 + c];
        uint2 h1 = Xs[(long long)adj[j + 1] * 32 + c];
        float2 a0 = __half22float2(*(__half2*)&h0.x), a1 = __half22float2(*(__half2*)&h0.y);
        float2 b0 = __half22float2(*(__half2*)&h1.x), b1 = __half22float2(*(__half2*)&h1.y);
        s0 += a0.x + b0.x; s1 += a0.y + b0.y;
        s2 += a1.x + b1.x; s3 += a1.y + b1.y;
    }
    if (j < end) {
        uint2 h0 = Xs[(long long)adj[j] * 32 + c];
        float2 a0 = __half22float2(*(__half2*)&h0.x), a1 = __half22float2(*(__half2*)&h0.y);
        s0 += a0.x; s1 += a0.y; s2 += a1.x; s3 += a1.y;
    }
    float w = dinv[node], w2 = w * w;
    float4 sv = xself[(long long)node * 32 + c];
    uint2 o;
    *(__half2*)&o.x = __floats2half2_rn(sv.x * w2 + s0 * w, sv.y * w2 + s1 * w);
    *(__half2*)&o.y = __floats2half2_rn(sv.z * w2 + s2 * w, sv.w * w2 + s3 * w);
    Xa[(long long)node * 32 + c] = o;
}

// GM=2: Out[node]  = dinv * sum Gs[adj]               (fp32 T1)
// GM=3: Out[node] += T[node] + dinv * sum Gs[adj]     (fp32 out, final join)
template <int GM>
__global__ __launch_bounds__(256) void k_gather_out(const int* __restrict__ rowptr,
                                                    const int* __restrict__ adj,
                                                    const float* __restrict__ dinv,
                                                    const uint2* __restrict__ Gs,
                                                    const float4* __restrict__ T,
                                                    float4* __restrict__ Out, int N) {
    int node = blockIdx.x * 8 + (threadIdx.x >> 5);
    int c = threadIdx.x & 31;
    if (node >= N) return;
    int beg = rowptr[node], end = rowptr[node + 1];
    float s0 = 0.f, s1 = 0.f, s2 = 0.f, s3 = 0.f;
    int j = beg;
    for (; j + 2 <= end; j += 2) {
        uint2 h0 = Gs[(long long)adj[j] * 32 + c];
        uint2 h1 = Gs[(long long)adj[j + 1] * 32 + c];
        float2 a0 = __half22float2(*(__half2*)&h0.x), a1 = __half22float2(*(__half2*)&h0.y);
        float2 b0 = __half22float2(*(__half2*)&h1.x), b1 = __half22float2(*(__half2*)&h1.y);
        s0 += a0.x + b0.x; s1 += a0.y + b0.y;
        s2 += a1.x + b1.x; s3 += a1.y + b1.y;
    }
    if (j < end) {
        uint2 h0 = Gs[(long long)adj[j] * 32 + c];
        float2 a0 = __half22float2(*(__half2*)&h0.x), a1 = __half22float2(*(__half2*)&h0.y);
        s0 += a0.x; s1 += a0.y; s2 += a1.x; s3 += a1.y;
    }
    float w = dinv[node];
    long long p = (long long)node * 32 + c;
    float4 a;
    if (GM == 2) {
        a = make_float4(0.f, 0.f, 0.f, 0.f);
    } else {
        float4 o = Out[p];
        float4 tv = T[p];
        a = make_float4(o.x + tv.x, o.y + tv.y, o.z + tv.z, o.w + tv.w);
    }
    a.x += s0 * w; a.y += s1 * w; a.z += s2 * w; a.w += s3 * w;
    Out[p] = a;
}

// ---------------------------------------------------------------------------
// fp16 tensor-core GEMM (m16n8k16, fp32 accum) with cp.async double buffering.
//   C = A[M,KT] * Wh^T  where Wh is [Ncol][KT] half (pre-transposed weights).
//   BM=128, BN=64, BK=32; 256 threads = 8 warps (4 M x 2 N), warp tile 32x32.
// MODE 0: OutH = half(relu(acc + bias2[c]))                       (layer 1)
// MODE 1: OutS = half(acc*dv) ; OutF  = acc*dv^2 + bias2 + bias3  (layer 2a)
// MODE 2: OutS = half(acc*dv) ; OutF += acc*dv^2                  (layer 2b)
// ---------------------------------------------------------------------------
__device__ __forceinline__ void mma_f16(float* c, uint32_t a0, uint32_t a1,
                                        uint32_t a2, uint32_t a3,
                                        uint32_t b0, uint32_t b1) {
    asm volatile(
        "mma.sync.aligned.m16n8k16.row.col.f32.f16.f16.f32 "
        "{%0,%1,%2,%3}, {%4,%5,%6,%7}, {%8,%9}, {%0,%1,%2,%3};\n"
        : "+f"(c[0]), "+f"(c[1]), "+f"(c[2]), "+f"(c[3])
        : "r"(a0), "r"(a1), "r"(a2), "r"(a3), "r"(b0), "r"(b1));
}

__device__ __forceinline__ uint32_t smem_u32(const void* p) {
    return (uint32_t)__cvta_generic_to_shared(p);
}
__device__ __forceinline__ void cp16(uint32_t dst, const void* src, int sz) {
    asm volatile("cp.async.cg.shared.global [%0], [%1], 16, %2;\n"
                 :: "r"(dst), "l"(src), "r"(sz));
}
__device__ __forceinline__ void cp_commit() {
    asm volatile("cp.async.commit_group;\n");
}
template <int N_> __device__ __forceinline__ void cp_wait() {
    asm volatile("cp.async.wait_group %0;\n" :: "n"(N_));
}

template <int MODE, int KT>
__global__ __launch_bounds__(256) void k_gemm_h(const __half* __restrict__ A,
                                                const __half* __restrict__ B,   // Wh [Ncol][KT]
                                                const float* __restrict__ dinv,
                                                __half* __restrict__ OutS,      // Gs half
                                                __half* __restrict__ OutH,      // H half
                                                float* __restrict__ OutF,       // out fp32
                                                const float* __restrict__ bias2,
                                                const float* __restrict__ bias3,
                                                int M, int Ncol) {
    __shared__ __half As[2][128 * 40];   // pad 40 halves/row
    __shared__ __half Bs[2][64 * 40];

    const int tid  = threadIdx.x;
    const int wid  = tid >> 5;
    const int lane = tid & 31;
    const int gid  = lane >> 2;     // 0..7
    const int tig  = lane & 3;      // 0..3
    const int wm   = wid >> 1;      // 0..3
    const int wn   = wid & 1;       // 0..1
    const int rowBase = blockIdx.y * 128;
    const int colBase = blockIdx.x * 64;
    constexpr int NK = KT / 32;

    auto loadTiles = [&](int i) {
        int k0 = i * 32;
        int buf = i & 1;
        // A: 128 rows x 32 half = 512 x 16B chunks, 2 per thread
#pragma unroll
        for (int t = 0; t < 2; t++) {
            int idx = tid + t * 256;        // 0..511
            int r   = idx >> 2;
            int ch  = idx & 3;
            int row = rowBase + r;
            const __half* g = A + (long long)(row < M ? row : 0) * KT + k0 + ch * 8;
            cp16(smem_u32(&As[buf][r * 40 + ch * 8]), g, row < M ? 16 : 0);
        }
        // B: 64 n-rows x 32 half = 256 chunks, 1 per thread
        {
            int n  = tid >> 2;
            int ch = tid & 3;
            const __half* g = B + (long long)(colBase + n) * KT + k0 + ch * 8;
            cp16(smem_u32(&Bs[buf][n * 40 + ch * 8]), g, 16);
        }
        cp_commit();
    };

    float acc[2][4][4] = {};
    loadTiles(0);

#pragma unroll
    for (int i = 0; i < NK; i++) {
        if (i + 1 < NK) loadTiles(i + 1);
        if (i + 1 < NK) cp_wait<1>(); else cp_wait<0>();
        __syncthreads();

        const __half* as = As[i & 1];
        const __half* bs = Bs[i & 1];
#pragma unroll
        for (int ks = 0; ks < 32; ks += 16) {
            uint32_t a[2][4];
#pragma unroll
            for (int mt = 0; mt < 2; mt++) {
                int r = wm * 32 + mt * 16 + gid;
                const uint32_t* p0 = (const uint32_t*)(as + r * 40 + ks + 2 * tig);
                const uint32_t* p1 = (const uint32_t*)(as + (r + 8) * 40 + ks + 2 * tig);
                a[mt][0] = p0[0];
                a[mt][1] = p1[0];
                a[mt][2] = p0[4];
                a[mt][3] = p1[4];
            }
            uint32_t b[4][2];
#pragma unroll
            for (int nt = 0; nt < 4; nt++) {
                int n = wn * 32 + nt * 8 + gid;
                const uint32_t* p = (const uint32_t*)(bs + n * 40 + ks + 2 * tig);
                b[nt][0] = p[0];
                b[nt][1] = p[4];
            }
#pragma unroll
            for (int mt = 0; mt < 2; mt++)
#pragma unroll
                for (int nt = 0; nt < 4; nt++)
                    mma_f16(acc[mt][nt], a[mt][0], a[mt][1], a[mt][2], a[mt][3],
                            b[nt][0], b[nt][1]);
        }
        __syncthreads();
    }

    // epilogue: c0,c1 -> row gid (cols 2tig,2tig+1); c2,c3 -> row gid+8
#pragma unroll
    for (int mt = 0; mt < 2; mt++) {
#pragma unroll
        for (int h = 0; h < 2; h++) {
            int row = rowBase + wm * 32 + mt * 16 + gid + h * 8;
            if (row >= M) continue;
            float dv  = (MODE == 0) ? 0.f : dinv[row];
            float dv2 = dv * dv;
            long long rb = (long long)row * Ncol;
#pragma unroll
            for (int nt = 0; nt < 4; nt++) {
                int c = colBase + wn * 32 + nt * 8 + 2 * tig;
                float v0 = acc[mt][nt][2 * h + 0];
                float v1 = acc[mt][nt][2 * h + 1];
                if (MODE == 0) {
                    float2 bb = *(const float2*)(bias2 + c);
                    *(__half2*)(OutH + rb + c) =
                        __floats2half2_rn(fmaxf(v0 + bb.x, 0.f), fmaxf(v1 + bb.y, 0.f));
                } else if (MODE == 1) {
                    *(__half2*)(OutS + rb + c) = __floats2half2_rn(v0 * dv, v1 * dv);
                    float2 p2 = *(const float2*)(bias2 + c);
                    float2 p3 = *(const float2*)(bias3 + c);
                    *(float2*)(OutF + rb + c) =
                        make_float2(v0 * dv2 + p2.x + p3.x, v1 * dv2 + p2.y + p3.y);
                } else {
                    *(__half2*)(OutS + rb + c) = __floats2half2_rn(v0 * dv, v1 * dv);
                    float2 o = *(const float2*)(OutF + rb + c);
                    o.x += v0 * dv2;
                    o.y += v1 * dv2;
                    *(float2*)(OutF + rb + c) = o;
                }
            }
        }
    }
}

// ---------------------------------------------------------------------------
// host side: two-stream overlapped schedule (graph-capture-legal fork/join).
// s2's FIRST operation is a wait on an event recorded in capturing stream s0.
// ---------------------------------------------------------------------------
static cudaStream_t g_s2   = nullptr;
static cudaEvent_t  g_evF  = nullptr;   // fork point (s0, first)
static cudaEvent_t  g_evW  = nullptr;   // weights prepped (s2)
static cudaEvent_t  g_evC  = nullptr;   // after convert+deg (s0)
static cudaEvent_t  g_evX1 = nullptr;   // after gather Xa1 (stagger gate, s0)
static cudaEvent_t  g_evH2 = nullptr;   // after GEMM H2 (s2)
static cudaEvent_t  g_evM1 = nullptr;   // after GEMM MODE1 (s0)
static cudaEvent_t  g_evT1 = nullptr;   // after gather T1 (s2, join point)

extern "C" void kernel_launch(void* const* d_in, const int* in_sizes, int n_in,
                              void* d_out, int out_size) {
    if (!g_s2) {
        cudaStreamCreateWithFlags(&g_s2, cudaStreamNonBlocking);
        cudaEventCreateWithFlags(&g_evF,  cudaEventDisableTiming);
        cudaEventCreateWithFlags(&g_evW,  cudaEventDisableTiming);
        cudaEventCreateWithFlags(&g_evC,  cudaEventDisableTiming);
        cudaEventCreateWithFlags(&g_evX1, cudaEventDisableTiming);
        cudaEventCreateWithFlags(&g_evH2, cudaEventDisableTiming);
        cudaEventCreateWithFlags(&g_evM1, cudaEventDisableTiming);
        cudaEventCreateWithFlags(&g_evT1, cudaEventDisableTiming);
    }

    const float* x   = (const float*)d_in[0];
    const void*  ei  = d_in[1];
    const void*  ei2 = d_in[2];
    const float* W0 = (const float*)d_in[3];
    const float* b0 = (const float*)d_in[4];
    const float* W1 = (const float*)d_in[5];
    const float* b1 = (const float*)d_in[6];
    const float* W2 = (const float*)d_in[7];
    const float* b2 = (const float*)d_in[8];
    const float* W3 = (const float*)d_in[9];
    const float* b3 = (const float*)d_in[10];

    const int N = in_sizes[0] / 128;   // 50000
    const int E = in_sizes[1] / 2;     // 800000
    const int NB = (N + 1023) / 1024;  // scan blocks

    float* S = nullptr;
    cudaGetSymbolAddress((void**)&S, g_scratch);
    float*  dinv1 = S + OFF_DINV1;
    float*  dinv2 = S + OFF_DINV2;
    int*    cnt1  = (int*)(S + OFF_CNT1);
    int*    cnt2  = (int*)(S + OFF_CNT2);
    int*    rp1   = (int*)(S + OFF_RP1);
    int*    rp2   = (int*)(S + OFF_RP2);
    int*    fp1   = (int*)(S + OFF_FP1);
    int*    fp2   = (int*)(S + OFF_FP2);
    int*    bs1   = (int*)(S + OFF_BS1);
    int*    bs2   = (int*)(S + OFF_BS2);
    int*    idx1  = (int*)(S + OFF_IDX1);
    int*    idx2  = (int*)(S + OFF_IDX2);
    int*    adj1  = (int*)(S + OFF_ADJ1);
    int*    adj2  = (int*)(S + OFF_ADJ2);
    __half* Xs1   = (__half*)(S + OFF_XS1);
    __half* Xs2   = (__half*)(S + OFF_XS2);
    __half* Xa1   = (__half*)(S + OFF_XA1);
    __half* Xa2   = (__half*)(S + OFF_XA2);
    __half* H1    = (__half*)(S + OFF_H1);
    __half* H2    = (__half*)(S + OFF_H2);
    __half* Gs1   = (__half*)(S + OFF_GS1);
    __half* Gs2   = (__half*)(S + OFF_GS2);
    float*  T1    = S + OFF_T1;
    __half* Wh0   = (__half*)(S + OFF_WH0);
    __half* Wh1   = (__half*)(S + OFF_WH1);
    __half* Wh2   = (__half*)(S + OFF_WH2);
    __half* Wh3   = (__half*)(S + OFF_WH3);
    float*  out   = (float*)d_out;

    cudaStream_t s0 = 0;
    cudaStream_t s2 = g_s2;

    const int* src1 = idx1;
    const int* dst1 = idx1 + E;
    const int* src2 = idx2;
    const int* dst2 = idx2 + E;

    // ---- s0: first kernel (dtype probe + zero counters), then FORK
    {
        int words = (E < 65536) ? E : 65536;
        int span  = (2 * N > words) ? 2 * N : words;
        k_detect_zero<<<(span + 255) / 256, 256, 0, s0>>>((const long long*)ei, words, N, cnt1, 2 * N);
    }
    cudaEventRecord(g_evF, s0);

    // ---- s2 joins capture via wait(evF), then weight prep (concurrent w/ decode)
    cudaStreamWaitEvent(s2, g_evF, 0);
    k_prep_w<<<512, 256, 0, s2>>>(W0, W1, W2, W3, Wh0, Wh1, Wh2, Wh3);
    cudaEventRecord(g_evW, s2);

    // ---- s0: decode + degree histogram
    k_convert_deg<<<(2 * E + 255) / 256, 256, 0, s0>>>(ei, ei2, idx1, idx2, 2 * E, E, cnt1, cnt2);
    cudaEventRecord(g_evC, s0);

    // ---- graph-1 chain on s0 (multi-block scan)
    k_scan_a<<<NB, 1024, 0, s0>>>(cnt1, rp1, dinv1, bs1, N);
    k_scan_b<<<1, 64, 0, s0>>>(bs1, NB, rp1, N);
    k_scan_c<<<NB, 1024, 0, s0>>>(rp1, fp1, bs1, N);
    k_fill1<<<(E + 255) / 256, 256, 0, s0>>>(src1, dst1, fp1, adj1, E);
    k_prescale_h<<<(N * 32 + 255) / 256, 256, 0, s0>>>((const float4*)x, dinv1, (uint2*)Xs1, N * 32);
    k_gather_xa<<<(N + 7) / 8, 256, 0, s0>>>(rp1, adj1, dinv1, (const uint2*)Xs1,
                                             (const float4*)x, (uint2*)Xa1, N);
    cudaEventRecord(g_evX1, s0);

    // ---- graph-2 chain on s2 (gather staggered after Xa1)
    cudaStreamWaitEvent(s2, g_evC, 0);
    k_scan_a<<<NB, 1024, 0, s2>>>(cnt2, rp2, dinv2, bs2, N);
    k_scan_b<<<1, 64, 0, s2>>>(bs2, NB, rp2, N);
    k_scan_c<<<NB, 1024, 0, s2>>>(rp2, fp2, bs2, N);
    k_fill1<<<(E + 255) / 256, 256, 0, s2>>>(src2, dst2, fp2, adj2, E);
    k_prescale_h<<<(N * 32 + 255) / 256, 256, 0, s2>>>((const float4*)x, dinv2, (uint2*)Xs2, N * 32);
    cudaStreamWaitEvent(s2, g_evX1, 0);
    k_gather_xa<<<(N + 7) / 8, 256, 0, s2>>>(rp2, adj2, dinv2, (const uint2*)Xs2,
                                             (const float4*)x, (uint2*)Xa2, N);

    // ---- layer-1 GEMMs: H = relu(Xa @ W + b)   (KT=128, Ncol=256)
    dim3 g1(4, (N + 127) / 128);
    cudaStreamWaitEvent(s0, g_evW, 0);
    k_gemm_h<0, 128><<<g1, 256, 0, s0>>>(Xa1, Wh0, nullptr, nullptr, H1, nullptr, b0, nullptr, N, 256);
    k_gemm_h<0, 128><<<g1, 256, 0, s2>>>(Xa2, Wh1, nullptr, nullptr, H2, nullptr, b1, nullptr, N, 256);
    cudaEventRecord(g_evH2, s2);

    // ---- layer-2 GEMMs (KT=256, Ncol=128)
    dim3 g2(2, (N + 127) / 128);
    k_gemm_h<1, 256><<<g2, 256, 0, s0>>>(H1, Wh2, dinv1, Gs1, nullptr, out, b2, b3, N, 128);
    cudaEventRecord(g_evM1, s0);

    // graph-1 output gather into T1 on s2, hidden under MODE2
    cudaStreamWaitEvent(s2, g_evM1, 0);
    k_gather_out<2><<<(N + 7) / 8, 256, 0, s2>>>(rp1, adj1, dinv1, (const uint2*)Gs1,
                                                 nullptr, (float4*)T1, N);
    cudaEventRecord(g_evT1, s2);

    cudaStreamWaitEvent(s0, g_evH2, 0);
    k_gemm_h<2, 256><<<g2, 256, 0, s0>>>(H2, Wh3, dinv2, Gs2, nullptr, out, nullptr, nullptr, N, 128);

    // ---- final: graph-2 gather + T1 add fused into out (join on evT1)
    cudaStreamWaitEvent(s0, g_evT1, 0);
    k_gather_out<3><<<(N + 7) / 8, 256, 0, s0>>>(rp2, adj2, dinv2, (const uint2*)Gs2,
                                                 (const float4*)T1, (float4*)out, N);
}

// round 14
// speedup vs baseline: 4.8129x; 1.0018x over previous
#include <cuda_runtime.h>
#include <cuda_fp16.h>
#include <cstdint>

// Problem constants (fixed by the reference)
constexpr long long Nn = 50000;
constexpr long long Ee = 800000;
constexpr long long RP = 50008;   // rowptr stride (>= Nn+1, multiple of 4)

// Scratch layout inside one __device__ array (units of float = 4B).
constexpr long long OFF_DINV1 = 0;
constexpr long long OFF_DINV2 = OFF_DINV1 + Nn;
constexpr long long OFF_CNT1  = OFF_DINV2 + Nn;            // int
constexpr long long OFF_CNT2  = OFF_CNT1  + Nn;            // int
constexpr long long OFF_RP1   = OFF_CNT2  + Nn;            // int rowptr
constexpr long long OFF_RP2   = OFF_RP1   + RP;
constexpr long long OFF_FP1   = OFF_RP2   + RP;            // int fill cursor
constexpr long long OFF_FP2   = OFF_FP1   + Nn;
constexpr long long OFF_BS1   = OFF_FP2   + Nn;            // int block sums [64]
constexpr long long OFF_BS2   = OFF_BS1   + 64;
constexpr long long OFF_IDX1  = OFF_BS2   + 64;            // src1,dst1 [2E] int
constexpr long long OFF_IDX2  = OFF_IDX1  + 2 * Ee;        // src2,dst2 [2E] int
constexpr long long OFF_ADJ1  = OFF_IDX2  + 2 * Ee;        // CSR adj   [E] int
constexpr long long OFF_ADJ2  = OFF_ADJ1  + Ee;
constexpr long long OFF_XS1   = OFF_ADJ2  + Ee;            // x*dinv1 half [N,128]
constexpr long long OFF_XS2   = OFF_XS1   + Nn * 64;
constexpr long long OFF_XA1   = OFF_XS2   + Nn * 64;       // agg(x) half  [N,128]
constexpr long long OFF_XA2   = OFF_XA1   + Nn * 64;
constexpr long long OFF_H1    = OFF_XA2   + Nn * 64;       // relu half    [N,256]
constexpr long long OFF_H2    = OFF_H1    + Nn * 128;
constexpr long long OFF_GS1   = OFF_H2    + Nn * 128;      // g*dinv half  [N,128]
constexpr long long OFF_GS2   = OFF_GS1   + Nn * 64;
constexpr long long OFF_T1    = OFF_GS2   + Nn * 64;       // graph1 term fp32 [N,128]
constexpr long long OFF_WH0   = OFF_T1    + Nn * 128;      // W0^T half [256][128]
constexpr long long OFF_WH1   = OFF_WH0   + 16384;
constexpr long long OFF_WH2   = OFF_WH1   + 16384;         // W2^T half [128][256]
constexpr long long OFF_WH3   = OFF_WH2   + 16384;
constexpr long long SCRATCH   = OFF_WH3   + 16384;

__device__ float g_scratch[SCRATCH];
// 1 if edge indices are int64, 0 if int32. Statically 1; k_detect_zero clears
// it iff the data is int32. Deterministic for fixed input.
__device__ int g_is64 = 1;

// ---------------------------------------------------------------------------
// detect (sampled) + zero degree counters
// ---------------------------------------------------------------------------
__global__ void k_detect_zero(const long long* __restrict__ p, int words, int n,
                              int* __restrict__ cnt, int nzero) {
    int i = blockIdx.x * blockDim.x + threadIdx.x;
    if (i < nzero) cnt[i] = 0;
    if (i < words) {
        long long v = p[i];
        if (v < 0 || v >= n) g_is64 = 0;   // benign race: all writers write 0
    }
}

// decode both graphs' indices + degree histogram (dst halves) in one pass
__global__ void k_convert_deg(const void* __restrict__ p1, const void* __restrict__ p2,
                              int* __restrict__ o1, int* __restrict__ o2,
                              int E2, int E, int* __restrict__ cnt1, int* __restrict__ cnt2) {
    int i = blockIdx.x * blockDim.x + threadIdx.x;
    if (i < E2) {
        int v1, v2;
        if (g_is64) {
            v1 = (int)((const long long*)p1)[i];
            v2 = (int)((const long long*)p2)[i];
        } else {
            v1 = ((const int*)p1)[i];
            v2 = ((const int*)p2)[i];
        }
        o1[i] = v1;
        o2[i] = v2;
        if (i >= E) {                       // dst halves
            atomicAdd(&cnt1[v1], 1);
            atomicAdd(&cnt2[v2], 1);
        }
    }
}

// ---------------------------------------------------------------------------
// multi-block exclusive scan (3 phases) + dinv compute
// ---------------------------------------------------------------------------
__global__ __launch_bounds__(1024) void k_scan_a(const int* __restrict__ cnt,
                                                 int* __restrict__ rp,
                                                 float* __restrict__ dinv,
                                                 int* __restrict__ bsum, int n) {
    __shared__ int wsum[32];
    const int t = threadIdx.x;
    const int lane = t & 31, wid = t >> 5;
    int i = blockIdx.x * 1024 + t;
    int v = (i < n) ? cnt[i] : 0;
    if (i < n) dinv[i] = rsqrtf((float)v + 1.0f);
    int incl = v;
#pragma unroll
    for (int off = 1; off < 32; off <<= 1) {
        int x = __shfl_up_sync(0xffffffffu, incl, off);
        if (lane >= off) incl += x;
    }
    if (lane == 31) wsum[wid] = incl;
    __syncthreads();
    if (wid == 0) {
        int s = wsum[lane];
#pragma unroll
        for (int off = 1; off < 32; off <<= 1) {
            int x = __shfl_up_sync(0xffffffffu, s, off);
            if (lane >= off) s += x;
        }
        wsum[lane] = s;
    }
    __syncthreads();
    int warpoff = (wid == 0) ? 0 : wsum[wid - 1];
    if (i < n) rp[i] = warpoff + incl - v;
    if (t == 0) bsum[blockIdx.x] = wsum[31];
}

__global__ void k_scan_b(int* __restrict__ bsum, int nb, int* __restrict__ rp, int n) {
    __shared__ int s[64];
    int t = threadIdx.x;
    int v = (t < nb) ? bsum[t] : 0;
    s[t] = v;
    __syncthreads();
#pragma unroll
    for (int off = 1; off < 64; off <<= 1) {
        int x = (t >= off) ? s[t - off] : 0;
        __syncthreads();
        s[t] += x;
        __syncthreads();
    }
    if (t < nb) bsum[t] = s[t] - v;        // exclusive
    if (t == nb - 1) rp[n] = s[t];         // grand total
}

__global__ __launch_bounds__(1024) void k_scan_c(int* __restrict__ rp, int* __restrict__ fp,
                                                 const int* __restrict__ bsum, int n) {
    int i = blockIdx.x * 1024 + threadIdx.x;
    if (i < n) {
        int v = rp[i] + bsum[blockIdx.x];
        rp[i] = v;
        fp[i] = v;
    }
}

__global__ void k_fill1(const int* __restrict__ src, const int* __restrict__ dst,
                        int* __restrict__ fp, int* __restrict__ adj, int E) {
    int e = blockIdx.x * blockDim.x + threadIdx.x;
    if (e < E) {
        int p = atomicAdd(&fp[dst[e]], 1);
        adj[p] = src[e];
    }
}

// prescale to half: Xs[i] = x[i] * dinv[row], packed half2x2 per float4
__global__ void k_prescale_h(const float4* __restrict__ x, const float* __restrict__ dinv,
                             uint2* __restrict__ Xs, int total4) {
    int i = blockIdx.x * blockDim.x + threadIdx.x;
    if (i < total4) {
        int row = i >> 5;
        float4 v = x[i];
        float d = dinv[row];
        uint2 o;
        *(__half2*)&o.x = __floats2half2_rn(v.x * d, v.y * d);
        *(__half2*)&o.y = __floats2half2_rn(v.z * d, v.w * d);
        Xs[i] = o;
    }
}

// weight prep: Wh[n*K + k] = half(W[k*N + n])  (transpose + halve, all 4)
__global__ void k_prep_w(const float* __restrict__ W0, const float* __restrict__ W1,
                         const float* __restrict__ W2, const float* __restrict__ W3,
                         __half* __restrict__ Wh0, __half* __restrict__ Wh1,
                         __half* __restrict__ Wh2, __half* __restrict__ Wh3) {
    int id = blockIdx.x * 256 + threadIdx.x;       // 0..131071
    int seg = id >> 15;
    int local = id & 32767;
    const float* W;
    __half* Wh;
    int K, Nc;
    if (seg == 0)      { W = W0; Wh = Wh0; K = 128; Nc = 256; }
    else if (seg == 1) { W = W1; Wh = Wh1; K = 128; Nc = 256; }
    else if (seg == 2) { W = W2; Wh = Wh2; K = 256; Nc = 128; }
    else               { W = W3; Wh = Wh3; K = 256; Nc = 128; }
    int k = local / Nc, n = local % Nc;            // coalesced read
    Wh[n * K + k] = __float2half_rn(W[local]);
}

// ---------------------------------------------------------------------------
// gathers (half2 payload, fp32 accumulate). One warp per node, 4 cols/thread.
// ---------------------------------------------------------------------------
// Xa[node] = half( x[node]*dinv^2 + dinv * sum Xs[adj] )
__global__ __launch_bounds__(256) void k_gather_xa(const int* __restrict__ rowptr,
                                                   const int* __restrict__ adj,
                                                   const float* __restrict__ dinv,
                                                   const uint2* __restrict__ Xs,
                                                   const float4* __restrict__ xself,
                                                   uint2* __restrict__ Xa, int N) {
    int node = blockIdx.x * 8 + (threadIdx.x >> 5);
    int c = threadIdx.x & 31;
    if (node >= N) return;
    int beg = rowptr[node], end = rowptr[node + 1];
    float s0 = 0.f, s1 = 0.f, s2 = 0.f, s3 = 0.f;
    int j = beg;
    for (; j + 2 <= end; j += 2) {
        uint2 h0 = Xs[(long long)adj[j] * 32 + c];
        uint2 h1 = Xs[(long long)adj[j + 1] * 32 + c];
        float2 a0 = __half22float2(*(__half2*)&h0.x), a1 = __half22float2(*(__half2*)&h0.y);
        float2 b0 = __half22float2(*(__half2*)&h1.x), b1 = __half22float2(*(__half2*)&h1.y);
        s0 += a0.x + b0.x; s1 += a0.y + b0.y;
        s2 += a1.x + b1.x; s3 += a1.y + b1.y;
    }
    if (j < end) {
        uint2 h0 = Xs[(long long)adj[j] * 32 + c];
        float2 a0 = __half22float2(*(__half2*)&h0.x), a1 = __half22float2(*(__half2*)&h0.y);
        s0 += a0.x; s1 += a0.y; s2 += a1.x; s3 += a1.y;
    }
    float w = dinv[node], w2 = w * w;
    float4 sv = xself[(long long)node * 32 + c];
    uint2 o;
    *(__half2*)&o.x = __floats2half2_rn(sv.x * w2 + s0 * w, sv.y * w2 + s1 * w);
    *(__half2*)&o.y = __floats2half2_rn(sv.z * w2 + s2 * w, sv.w * w2 + s3 * w);
    Xa[(long long)node * 32 + c] = o;
}

// GM=2: Out[node]  = dinv * sum Gs[adj]               (fp32 T1)
// GM=3: Out[node] += T[node] + dinv * sum Gs[adj]     (fp32 out, final join)
template <int GM>
__global__ __launch_bounds__(256) void k_gather_out(const int* __restrict__ rowptr,
                                                    const int* __restrict__ adj,
                                                    const float* __restrict__ dinv,
                                                    const uint2* __restrict__ Gs,
                                                    const float4* __restrict__ T,
                                                    float4* __restrict__ Out, int N) {
    int node = blockIdx.x * 8 + (threadIdx.x >> 5);
    int c = threadIdx.x & 31;
    if (node >= N) return;
    int beg = rowptr[node], end = rowptr[node + 1];
    float s0 = 0.f, s1 = 0.f, s2 = 0.f, s3 = 0.f;
    int j = beg;
    for (; j + 2 <= end; j += 2) {
        uint2 h0 = Gs[(long long)adj[j] * 32 + c];
        uint2 h1 = Gs[(long long)adj[j + 1] * 32 + c];
        float2 a0 = __half22float2(*(__half2*)&h0.x), a1 = __half22float2(*(__half2*)&h0.y);
        float2 b0 = __half22float2(*(__half2*)&h1.x), b1 = __half22float2(*(__half2*)&h1.y);
        s0 += a0.x + b0.x; s1 += a0.y + b0.y;
        s2 += a1.x + b1.x; s3 += a1.y + b1.y;
    }
    if (j < end) {
        uint2 h0 = Gs[(long long)adj[j] * 32 + c];
        float2 a0 = __half22float2(*(__half2*)&h0.x), a1 = __half22float2(*(__half2*)&h0.y);
        s0 += a0.x; s1 += a0.y; s2 += a1.x; s3 += a1.y;
    }
    float w = dinv[node];
    long long p = (long long)node * 32 + c;
    float4 a;
    if (GM == 2) {
        a = make_float4(0.f, 0.f, 0.f, 0.f);
    } else {
        float4 o = Out[p];
        float4 tv = T[p];
        a = make_float4(o.x + tv.x, o.y + tv.y, o.z + tv.z, o.w + tv.w);
    }
    a.x += s0 * w; a.y += s1 * w; a.z += s2 * w; a.w += s3 * w;
    Out[p] = a;
}

// ---------------------------------------------------------------------------
// fp16 tensor-core GEMM (m16n8k16, fp32 accum), cp.async double buffering,
// ldmatrix fragment loads (8 LDSM.x4 per 32-k block instead of 32 LDS.32).
//   C = A[M,KT] * Wh^T  where Wh is [Ncol][KT] half (pre-transposed weights).
//   BM=128, BN=64, BK=32; 256 threads = 8 warps (4 M x 2 N), warp tile 32x32.
//   pad-40 rows: ldmatrix row stride 80B -> 8 distinct 16B slots mod 128B.
// MODE 0: OutH = half(relu(acc + bias2[c]))                       (layer 1)
// MODE 1: OutS = half(acc*dv) ; OutF  = acc*dv^2 + bias2 + bias3  (layer 2a)
// MODE 2: OutS = half(acc*dv) ; OutF += acc*dv^2                  (layer 2b)
// ---------------------------------------------------------------------------
__device__ __forceinline__ void mma_f16(float* c, uint32_t a0, uint32_t a1,
                                        uint32_t a2, uint32_t a3,
                                        uint32_t b0, uint32_t b1) {
    asm volatile(
        "mma.sync.aligned.m16n8k16.row.col.f32.f16.f16.f32 "
        "{%0,%1,%2,%3}, {%4,%5,%6,%7}, {%8,%9}, {%0,%1,%2,%3};\n"
        : "+f"(c[0]), "+f"(c[1]), "+f"(c[2]), "+f"(c[3])
        : "r"(a0), "r"(a1), "r"(a2), "r"(a3), "r"(b0), "r"(b1));
}

__device__ __forceinline__ uint32_t smem_u32(const void* p) {
    return (uint32_t)__cvta_generic_to_shared(p);
}
__device__ __forceinline__ void ldsm_x4(uint32_t& r0, uint32_t& r1,
                                        uint32_t& r2, uint32_t& r3, uint32_t addr) {
    asm volatile("ldmatrix.sync.aligned.m8n8.x4.shared.b16 {%0,%1,%2,%3}, [%4];"
                 : "=r"(r0), "=r"(r1), "=r"(r2), "=r"(r3) : "r"(addr));
}
__device__ __forceinline__ void cp16(uint32_t dst, const void* src, int sz) {
    asm volatile("cp.async.cg.shared.global [%0], [%1], 16, %2;\n"
                 :: "r"(dst), "l"(src), "r"(sz));
}
__device__ __forceinline__ void cp_commit() {
    asm volatile("cp.async.commit_group;\n");
}
template <int N_> __device__ __forceinline__ void cp_wait() {
    asm volatile("cp.async.wait_group %0;\n" :: "n"(N_));
}

template <int MODE, int KT>
__global__ __launch_bounds__(256) void k_gemm_h(const __half* __restrict__ A,
                                                const __half* __restrict__ B,   // Wh [Ncol][KT]
                                                const float* __restrict__ dinv,
                                                __half* __restrict__ OutS,      // Gs half
                                                __half* __restrict__ OutH,      // H half
                                                float* __restrict__ OutF,       // out fp32
                                                const float* __restrict__ bias2,
                                                const float* __restrict__ bias3,
                                                int M, int Ncol) {
    __shared__ __half As[2][128 * 40];   // pad 40 halves/row
    __shared__ __half Bs[2][64 * 40];

    const int tid  = threadIdx.x;
    const int wid  = tid >> 5;
    const int lane = tid & 31;
    const int gid  = lane >> 2;     // 0..7
    const int tig  = lane & 3;      // 0..3
    const int wm   = wid >> 1;      // 0..3
    const int wn   = wid & 1;       // 0..1
    const int rowBase = blockIdx.y * 128;
    const int colBase = blockIdx.x * 64;
    constexpr int NK = KT / 32;

    auto loadTiles = [&](int i) {
        int k0 = i * 32;
        int buf = i & 1;
        // A: 128 rows x 32 half = 512 x 16B chunks, 2 per thread
#pragma unroll
        for (int t = 0; t < 2; t++) {
            int idx = tid + t * 256;        // 0..511
            int r   = idx >> 2;
            int ch  = idx & 3;
            int row = rowBase + r;
            const __half* g = A + (long long)(row < M ? row : 0) * KT + k0 + ch * 8;
            cp16(smem_u32(&As[buf][r * 40 + ch * 8]), g, row < M ? 16 : 0);
        }
        // B: 64 n-rows x 32 half = 256 chunks, 1 per thread
        {
            int n  = tid >> 2;
            int ch = tid & 3;
            const __half* g = B + (long long)(colBase + n) * KT + k0 + ch * 8;
            cp16(smem_u32(&Bs[buf][n * 40 + ch * 8]), g, 16);
        }
        cp_commit();
    };

    float acc[2][4][4] = {};
    loadTiles(0);

    // ldmatrix lane-address components (constant across iterations)
    const int aRow = (lane & 15);            // row within warp M-tile
    const int aKof = (lane >> 4) << 3;       // 0 or 8 (k-half)
    const int bRow = wn * 32 + lane;         // n row for B x4 (4 nt matrices)

#pragma unroll
    for (int i = 0; i < NK; i++) {
        if (i + 1 < NK) loadTiles(i + 1);
        if (i + 1 < NK) cp_wait<1>(); else cp_wait<0>();
        __syncthreads();

        const __half* as = As[i & 1];
        const __half* bs = Bs[i & 1];
#pragma unroll
        for (int ks = 0; ks < 32; ks += 16) {
            uint32_t a[2][4];
#pragma unroll
            for (int mt = 0; mt < 2; mt++) {
                uint32_t addr = smem_u32(as + (wm * 32 + mt * 16 + aRow) * 40 + ks + aKof);
                ldsm_x4(a[mt][0], a[mt][1], a[mt][2], a[mt][3], addr);
            }
            uint32_t b[2][4];   // [k-half][nt]
#pragma unroll
            for (int h = 0; h < 2; h++) {
                uint32_t addr = smem_u32(bs + bRow * 40 + ks + h * 8);
                ldsm_x4(b[h][0], b[h][1], b[h][2], b[h][3], addr);
            }
#pragma unroll
            for (int mt = 0; mt < 2; mt++)
#pragma unroll
                for (int nt = 0; nt < 4; nt++)
                    mma_f16(acc[mt][nt], a[mt][0], a[mt][1], a[mt][2], a[mt][3],
                            b[0][nt], b[1][nt]);
        }
        __syncthreads();
    }

    // epilogue: c0,c1 -> row gid (cols 2tig,2tig+1); c2,c3 -> row gid+8
#pragma unroll
    for (int mt = 0; mt < 2; mt++) {
#pragma unroll
        for (int h = 0; h < 2; h++) {
            int row = rowBase + wm * 32 + mt * 16 + gid + h * 8;
            if (row >= M) continue;
            float dv  = (MODE == 0) ? 0.f : dinv[row];
            float dv2 = dv * dv;
            long long rb = (long long)row * Ncol;
#pragma unroll
            for (int nt = 0; nt < 4; nt++) {
                int c = colBase + wn * 32 + nt * 8 + 2 * tig;
                float v0 = acc[mt][nt][2 * h + 0];
                float v1 = acc[mt][nt][2 * h + 1];
                if (MODE == 0) {
                    float2 bb = *(const float2*)(bias2 + c);
                    *(__half2*)(OutH + rb + c) =
                        __floats2half2_rn(fmaxf(v0 + bb.x, 0.f), fmaxf(v1 + bb.y, 0.f));
                } else if (MODE == 1) {
                    *(__half2*)(OutS + rb + c) = __floats2half2_rn(v0 * dv, v1 * dv);
                    float2 p2 = *(const float2*)(bias2 + c);
                    float2 p3 = *(const float2*)(bias3 + c);
                    *(float2*)(OutF + rb + c) =
                        make_float2(v0 * dv2 + p2.x + p3.x, v1 * dv2 + p2.y + p3.y);
                } else {
                    *(__half2*)(OutS + rb + c) = __floats2half2_rn(v0 * dv, v1 * dv);
                    float2 o = *(const float2*)(OutF + rb + c);
                    o.x += v0 * dv2;
                    o.y += v1 * dv2;
                    *(float2*)(OutF + rb + c) = o;
                }
            }
        }
    }
}

// ---------------------------------------------------------------------------
// host side: two-stream overlapped schedule (graph-capture-legal fork/join).
// s2's FIRST operation is a wait on an event recorded in capturing stream s0.
// ---------------------------------------------------------------------------
static cudaStream_t g_s2   = nullptr;
static cudaEvent_t  g_evF  = nullptr;   // fork point (s0, first)
static cudaEvent_t  g_evW  = nullptr;   // weights prepped (s2)
static cudaEvent_t  g_evC  = nullptr;   // after convert+deg (s0)
static cudaEvent_t  g_evX1 = nullptr;   // after gather Xa1 (stagger gate, s0)
static cudaEvent_t  g_evH2 = nullptr;   // after GEMM H2 (s2)
static cudaEvent_t  g_evM1 = nullptr;   // after GEMM MODE1 (s0)
static cudaEvent_t  g_evT1 = nullptr;   // after gather T1 (s2, join point)

extern "C" void kernel_launch(void* const* d_in, const int* in_sizes, int n_in,
                              void* d_out, int out_size) {
    if (!g_s2) {
        cudaStreamCreateWithFlags(&g_s2, cudaStreamNonBlocking);
        cudaEventCreateWithFlags(&g_evF,  cudaEventDisableTiming);
        cudaEventCreateWithFlags(&g_evW,  cudaEventDisableTiming);
        cudaEventCreateWithFlags(&g_evC,  cudaEventDisableTiming);
        cudaEventCreateWithFlags(&g_evX1, cudaEventDisableTiming);
        cudaEventCreateWithFlags(&g_evH2, cudaEventDisableTiming);
        cudaEventCreateWithFlags(&g_evM1, cudaEventDisableTiming);
        cudaEventCreateWithFlags(&g_evT1, cudaEventDisableTiming);
    }

    const float* x   = (const float*)d_in[0];
    const void*  ei  = d_in[1];
    const void*  ei2 = d_in[2];
    const float* W0 = (const float*)d_in[3];
    const float* b0 = (const float*)d_in[4];
    const float* W1 = (const float*)d_in[5];
    const float* b1 = (const float*)d_in[6];
    const float* W2 = (const float*)d_in[7];
    const float* b2 = (const float*)d_in[8];
    const float* W3 = (const float*)d_in[9];
    const float* b3 = (const float*)d_in[10];

    const int N = in_sizes[0] / 128;   // 50000
    const int E = in_sizes[1] / 2;     // 800000
    const int NB = (N + 1023) / 1024;  // scan blocks

    float* S = nullptr;
    cudaGetSymbolAddress((void**)&S, g_scratch);
    float*  dinv1 = S + OFF_DINV1;
    float*  dinv2 = S + OFF_DINV2;
    int*    cnt1  = (int*)(S + OFF_CNT1);
    int*    cnt2  = (int*)(S + OFF_CNT2);
    int*    rp1   = (int*)(S + OFF_RP1);
    int*    rp2   = (int*)(S + OFF_RP2);
    int*    fp1   = (int*)(S + OFF_FP1);
    int*    fp2   = (int*)(S + OFF_FP2);
    int*    bs1   = (int*)(S + OFF_BS1);
    int*    bs2   = (int*)(S + OFF_BS2);
    int*    idx1  = (int*)(S + OFF_IDX1);
    int*    idx2  = (int*)(S + OFF_IDX2);
    int*    adj1  = (int*)(S + OFF_ADJ1);
    int*    adj2  = (int*)(S + OFF_ADJ2);
    __half* Xs1   = (__half*)(S + OFF_XS1);
    __half* Xs2   = (__half*)(S + OFF_XS2);
    __half* Xa1   = (__half*)(S + OFF_XA1);
    __half* Xa2   = (__half*)(S + OFF_XA2);
    __half* H1    = (__half*)(S + OFF_H1);
    __half* H2    = (__half*)(S + OFF_H2);
    __half* Gs1   = (__half*)(S + OFF_GS1);
    __half* Gs2   = (__half*)(S + OFF_GS2);
    float*  T1    = S + OFF_T1;
    __half* Wh0   = (__half*)(S + OFF_WH0);
    __half* Wh1   = (__half*)(S + OFF_WH1);
    __half* Wh2   = (__half*)(S + OFF_WH2);
    __half* Wh3   = (__half*)(S + OFF_WH3);
    float*  out   = (float*)d_out;

    cudaStream_t s0 = 0;
    cudaStream_t s2 = g_s2;

    const int* src1 = idx1;
    const int* dst1 = idx1 + E;
    const int* src2 = idx2;
    const int* dst2 = idx2 + E;

    // ---- s0: first kernel (dtype probe + zero counters), then FORK
    {
        int words = (E < 65536) ? E : 65536;
        int span  = (2 * N > words) ? 2 * N : words;
        k_detect_zero<<<(span + 255) / 256, 256, 0, s0>>>((const long long*)ei, words, N, cnt1, 2 * N);
    }
    cudaEventRecord(g_evF, s0);

    // ---- s2 joins capture via wait(evF), then weight prep (concurrent w/ decode)
    cudaStreamWaitEvent(s2, g_evF, 0);
    k_prep_w<<<512, 256, 0, s2>>>(W0, W1, W2, W3, Wh0, Wh1, Wh2, Wh3);
    cudaEventRecord(g_evW, s2);

    // ---- s0: decode + degree histogram
    k_convert_deg<<<(2 * E + 255) / 256, 256, 0, s0>>>(ei, ei2, idx1, idx2, 2 * E, E, cnt1, cnt2);
    cudaEventRecord(g_evC, s0);

    // ---- graph-1 chain on s0 (multi-block scan)
    k_scan_a<<<NB, 1024, 0, s0>>>(cnt1, rp1, dinv1, bs1, N);
    k_scan_b<<<1, 64, 0, s0>>>(bs1, NB, rp1, N);
    k_scan_c<<<NB, 1024, 0, s0>>>(rp1, fp1, bs1, N);
    k_fill1<<<(E + 255) / 256, 256, 0, s0>>>(src1, dst1, fp1, adj1, E);
    k_prescale_h<<<(N * 32 + 255) / 256, 256, 0, s0>>>((const float4*)x, dinv1, (uint2*)Xs1, N * 32);
    k_gather_xa<<<(N + 7) / 8, 256, 0, s0>>>(rp1, adj1, dinv1, (const uint2*)Xs1,
                                             (const float4*)x, (uint2*)Xa1, N);
    cudaEventRecord(g_evX1, s0);

    // ---- graph-2 chain on s2 (gather staggered after Xa1)
    cudaStreamWaitEvent(s2, g_evC, 0);
    k_scan_a<<<NB, 1024, 0, s2>>>(cnt2, rp2, dinv2, bs2, N);
    k_scan_b<<<1, 64, 0, s2>>>(bs2, NB, rp2, N);
    k_scan_c<<<NB, 1024, 0, s2>>>(rp2, fp2, bs2, N);
    k_fill1<<<(E + 255) / 256, 256, 0, s2>>>(src2, dst2, fp2, adj2, E);
    k_prescale_h<<<(N * 32 + 255) / 256, 256, 0, s2>>>((const float4*)x, dinv2, (uint2*)Xs2, N * 32);
    cudaStreamWaitEvent(s2, g_evX1, 0);
    k_gather_xa<<<(N + 7) / 8, 256, 0, s2>>>(rp2, adj2, dinv2, (const uint2*)Xs2,
                                             (const float4*)x, (uint2*)Xa2, N);

    // ---- layer-1 GEMMs: H = relu(Xa @ W + b)   (KT=128, Ncol=256)
    dim3 g1(4, (N + 127) / 128);
    cudaStreamWaitEvent(s0, g_evW, 0);
    k_gemm_h<0, 128><<<g1, 256, 0, s0>>>(Xa1, Wh0, nullptr, nullptr, H1, nullptr, b0, nullptr, N, 256);
    k_gemm_h<0, 128><<<g1, 256, 0, s2>>>(Xa2, Wh1, nullptr, nullptr, H2, nullptr, b1, nullptr, N, 256);
    cudaEventRecord(g_evH2, s2);

    // ---- layer-2 GEMMs (KT=256, Ncol=128)
    dim3 g2(2, (N + 127) / 128);
    k_gemm_h<1, 256><<<g2, 256, 0, s0>>>(H1, Wh2, dinv1, Gs1, nullptr, out, b2, b3, N, 128);
    cudaEventRecord(g_evM1, s0);

    // graph-1 output gather into T1 on s2, hidden under MODE2
    cudaStreamWaitEvent(s2, g_evM1, 0);
    k_gather_out<2><<<(N + 7) / 8, 256, 0, s2>>>(rp1, adj1, dinv1, (const uint2*)Gs1,
                                                 nullptr, (float4*)T1, N);
    cudaEventRecord(g_evT1, s2);

    cudaStreamWaitEvent(s0, g_evH2, 0);
    k_gemm_h<2, 256><<<g2, 256, 0, s0>>>(H2, Wh3, dinv2, Gs2, nullptr, out, nullptr, nullptr, N, 128);

    // ---- final: graph-2 gather + T1 add fused into out (join on evT1)
    cudaStreamWaitEvent(s0, g_evT1, 0);
    k_gather_out<3><<<(N + 7) / 8, 256, 0, s0>>>(rp2, adj2, dinv2, (const uint2*)Gs2,
                                                 (const float4*)T1, (float4*)out, N);
}